// round 9
// baseline (speedup 1.0000x reference)
#include <cuda_runtime.h>
#include <cuda_bf16.h>
#include <stdint.h>

#define NBATCH 8
#define SEQ    4096
#define DIM    256
#define NTOK   (NBATCH * SEQ)                 // 32768
#define PROJ_ELEMS (NTOK * DIM)               // 8388608
#define S_ELEMS ((long long)NBATCH * SEQ * SEQ)

// ---------------- scratch (static device arrays) ---------------------------
// g_S: fp32 scores; softmax overwrites each 4096-float row in place with
// 4096 hi-bf16 + 4096 lo-bf16 of normalized P.
__device__ __align__(16) float          g_S[S_ELEMS];                 // 537 MB
__device__ __align__(16) unsigned short g_wh[3][DIM * DIM];
__device__ __align__(16) unsigned short g_wl[3][DIM * DIM];
__device__ __align__(16) unsigned short g_qh[PROJ_ELEMS], g_ql[PROJ_ELEMS];
__device__ __align__(16) unsigned short g_kh[PROJ_ELEMS], g_kl[PROJ_ELEMS];
__device__ __align__(16) unsigned short g_vth[PROJ_ELEMS], g_vtl[PROJ_ELEMS];

// ---------------- helpers ---------------------------------------------------
__device__ __forceinline__ uint32_t smem_u32(const void* p) {
    uint32_t a;
    asm("{ .reg .u64 t; cvta.to.shared.u64 t, %1; cvt.u32.u64 %0, t; }"
        : "=r"(a) : "l"(p));
    return a;
}

#define CP16(dst, src) \
    asm volatile("cp.async.cg.shared.global [%0], [%1], 16;" \
                 :: "r"(dst), "l"(src) : "memory")
#define CP_COMMIT()  asm volatile("cp.async.commit_group;" ::: "memory")
#define CP_WAIT1()   asm volatile("cp.async.wait_group 1;" ::: "memory")
#define CP_WAIT0()   asm volatile("cp.async.wait_group 0;" ::: "memory")

#define LDSM4(r, addr) \
    asm volatile("ldmatrix.sync.aligned.m8n8.x4.shared.b16 {%0,%1,%2,%3}, [%4];" \
                 : "=r"((r)[0]), "=r"((r)[1]), "=r"((r)[2]), "=r"((r)[3]) \
                 : "r"(addr))

#define MMA(d, a, b) \
    asm volatile("mma.sync.aligned.m16n8k16.row.col.f32.bf16.bf16.f32 " \
                 "{%0,%1,%2,%3},{%4,%5,%6,%7},{%8,%9},{%0,%1,%2,%3};" \
                 : "+f"((d)[0]), "+f"((d)[1]), "+f"((d)[2]), "+f"((d)[3]) \
                 : "r"((a)[0]), "r"((a)[1]), "r"((a)[2]), "r"((a)[3]), \
                   "r"((b)[0]), "r"((b)[1]))

__device__ __forceinline__ void split_bf(float x, unsigned short& h, unsigned short& l) {
    __nv_bfloat16 hb = __float2bfloat16_rn(x);
    float r = x - __bfloat162float(hb);
    __nv_bfloat16 lb = __float2bfloat16_rn(r);
    h = __bfloat16_as_ushort(hb);
    l = __bfloat16_as_ushort(lb);
}

// smem: per-stage A (2 splits x 128 rows x 64 bf16 = 128B rows, XOR-swizzled)
//       and B (2 splits x 256 rows x 64 bf16).
#define A_SP        16384                 // 128 * 128B
#define B_SP        32768                 // 256 * 128B
#define STAGE_BYTES (2 * A_SP + 2 * B_SP) // 98304
#define SMEM_TOTAL  (2 * STAGE_BYTES)     // 196608
#define SWB(kbyte, r) ((kbyte) ^ (((r) & 7) << 4))

// ---------------------------------------------------------------------------
// Split-bf16 mma.sync GEMM. Block tile 128x256, 256 threads (8 warps, 2x4,
// warp tile 64x64), K chunks of 64, 2-stage cp.async double buffer.
// 3 MMAs per product (hi*hi + hi*lo + lo*hi), fp32 accumulate, issued
// combo-major so each accumulator's reuse distance is 8 MMAs (covers HMMA
// latency at 2 warps/SMSP).
//   CFG 0 (proj):   z selects q/k/v. A = fp32 input (split in staging),
//                   B = g_wh/g_wl[z], K=256, N=256 in one tile. Epilogue:
//                   +bias -> z<2: split to g_qh/g_ql | g_kh/g_kl;
//                   z=2: transpose via smem -> g_vth/g_vtl [b][d][sq].
//   CFG 1 (scores): A=q, B=k (batch z), K=256, fp32 -> g_S[z].
//   CFG 2 (ctx):    A = P hi/lo rows in g_S (ld 8192, lo at +4096),
//                   B = vt, K=4096, fp32 -> out. N=256 in one tile.
// ---------------------------------------------------------------------------
template<int CFG>
__global__ __launch_bounds__(256, 1)
void gemm_kernel(const float* __restrict__ in_q, const float* __restrict__ in_k,
                 const float* __restrict__ in_v,
                 const float* __restrict__ bq, const float* __restrict__ bk,
                 const float* __restrict__ bv, float* __restrict__ out)
{
    constexpr int K  = (CFG == 2) ? 4096 : 256;
    constexpr int NC = K / 64;
    constexpr long long LDA = (CFG == 2) ? 8192 : 256;
    constexpr long long LDB = (CFG == 2) ? 4096 : 256;

    extern __shared__ __align__(128) char sm[];
    const uint32_t smb = smem_u32(sm);
    const int tid = threadIdx.x;
    const int w = tid >> 5, lane = tid & 31;
    const int wm = w & 1, wn = w >> 1;          // 2 x 4 warp grid
    const int m0 = blockIdx.x * 128, n0 = blockIdx.y * 256;
    const int z = blockIdx.z;

    const float* Afp = nullptr;
    const unsigned short *sp0 = nullptr, *sp1 = nullptr, *sp2 = nullptr, *sp3 = nullptr;
    if (CFG == 0) {
        Afp = (z == 0 ? in_q : z == 1 ? in_k : in_v) + (long long)m0 * 256;
        sp2 = g_wh[z];
        sp3 = g_wl[z];
    } else if (CFG == 1) {
        long long b = z;
        sp0 = g_qh + (b * SEQ + m0) * 256;
        sp1 = g_ql + (b * SEQ + m0) * 256;
        sp2 = g_kh + (b * SEQ + n0) * 256;
        sp3 = g_kl + (b * SEQ + n0) * 256;
    } else {
        long long b = z;
        sp0 = reinterpret_cast<const unsigned short*>(g_S)
              + b * SEQ * 8192 + (long long)m0 * 8192;
        sp1 = sp0 + 4096;
        sp2 = g_vth + b * (long long)DIM * SEQ;
        sp3 = g_vtl + b * (long long)DIM * SEQ;
    }

    float acc[4][8][4] = {};    // [mt 16-rows][nt 8-cols][frag]

    auto stage = [&](int c) {
        const int buf = c & 1;
        const uint32_t sb = smb + buf * STAGE_BYTES;
        char* sbp = sm + buf * STAGE_BYTES;
        const int k0 = c * 64;
        if (CFG == 0) {
            // A fp32 -> hi/lo bf16 split in registers, STS
#pragma unroll
            for (int t = tid; t < 2048; t += 256) {
                int r = t >> 4, kq = (t & 15) * 4;       // 128 rows x 16 float4
                float4 v = *reinterpret_cast<const float4*>(Afp + r * 256 + k0 + kq);
                ushort4 hh, ll;
                split_bf(v.x, hh.x, ll.x); split_bf(v.y, hh.y, ll.y);
                split_bf(v.z, hh.z, ll.z); split_bf(v.w, hh.w, ll.w);
                int off = r * 128 + SWB(kq * 2, r);
                *reinterpret_cast<ushort4*>(sbp + off)        = hh;
                *reinterpret_cast<ushort4*>(sbp + A_SP + off) = ll;
            }
        } else {
#pragma unroll
            for (int t = tid; t < 2048; t += 256) {
                int sp = t >> 10, r = (t >> 3) & 127, kc = (t & 7) * 8;
                const unsigned short* src = (sp ? sp1 : sp0) + (long long)r * LDA + k0 + kc;
                CP16(sb + sp * A_SP + r * 128 + SWB(kc * 2, r), src);
            }
        }
#pragma unroll
        for (int t = tid; t < 4096; t += 256) {
            int sp = t >> 11, r = (t >> 3) & 255, kc = (t & 7) * 8;
            const unsigned short* src = (sp ? sp3 : sp2) + (long long)r * LDB + k0 + kc;
            CP16(sb + 2 * A_SP + sp * B_SP + r * 128 + SWB(kc * 2, r), src);
        }
        CP_COMMIT();
    };

    // ldmatrix per-thread constants
    const int a_r0 = wm * 64 + (lane & 7) + ((lane >> 3) & 1) * 8;   // + mt*16
    const int a_kb = (lane >> 4) * 16;
    const int b_n0 = wn * 64 + (lane & 7) + (lane >> 4) * 8;          // + g*16
    const int b_kb = ((lane >> 3) & 1) * 16;

    auto compute = [&](int buf) {
        const uint32_t sa = smb + buf * STAGE_BYTES;
        const uint32_t sbb = sa + 2 * A_SP;
#pragma unroll
        for (int ks = 0; ks < 4; ks++) {
            uint32_t Ahf[4][4], Alf[4][4];
#pragma unroll
            for (int mt = 0; mt < 4; mt++) {
                int row = a_r0 + mt * 16;
                uint32_t ad = sa + row * 128 + SWB(ks * 32 + a_kb, row);
                LDSM4(Ahf[mt], ad);
                LDSM4(Alf[mt], ad + A_SP);
            }
#pragma unroll
            for (int g = 0; g < 4; g++) {
                int nrow = b_n0 + g * 16;
                uint32_t bd = sbb + nrow * 128 + SWB(ks * 32 + b_kb, nrow);
                uint32_t Bh[4], Bl[4];
                LDSM4(Bh, bd);
                LDSM4(Bl, bd + B_SP);
                // combo-major issue order: each acc touched 3x with reuse
                // distance 8 MMAs.
#pragma unroll
                for (int combo = 0; combo < 3; combo++)
#pragma unroll
                    for (int mt = 0; mt < 4; mt++)
#pragma unroll
                        for (int sub = 0; sub < 2; sub++) {
                            int nt = g * 2 + sub;
                            const uint32_t* af =
                                (combo == 2) ? Alf[mt] : Ahf[mt];
                            const uint32_t* bf =
                                (combo == 1) ? (Bl + sub * 2) : (Bh + sub * 2);
                            MMA(acc[mt][nt], af, bf);
                        }
            }
        }
    };

    stage(0);
    for (int c = 0; c < NC; c++) {
        __syncthreads();                 // prior compute done before buffer reuse
        if (c + 1 < NC) stage(c + 1);
        if (c + 1 < NC) CP_WAIT1(); else CP_WAIT0();
        __syncthreads();
        compute(c & 1);
    }
    __syncthreads();

    // ---------------- epilogue ----------------
    if (CFG == 0) {
        const float* bias = (z == 0) ? bq : (z == 1) ? bk : bv;
        if (z < 2) {
            unsigned short* DH = (z == 0) ? g_qh : g_kh;
            unsigned short* DL = (z == 0) ? g_ql : g_kl;
#pragma unroll
            for (int mt = 0; mt < 4; mt++)
#pragma unroll
                for (int nt = 0; nt < 8; nt++) {
                    int m  = m0 + wm * 64 + mt * 16 + (lane >> 2);
                    int ng = wn * 64 + nt * 8 + (lane & 3) * 2;
                    float b0 = bias[ng], b1 = bias[ng + 1];
                    float* a = acc[mt][nt];
                    ushort2 h2, l2;
                    split_bf(a[0] + b0, h2.x, l2.x); split_bf(a[1] + b1, h2.y, l2.y);
                    *reinterpret_cast<ushort2*>(&DH[(long long)m * 256 + ng]) = h2;
                    *reinterpret_cast<ushort2*>(&DL[(long long)m * 256 + ng]) = l2;
                    split_bf(a[2] + b0, h2.x, l2.x); split_bf(a[3] + b1, h2.y, l2.y);
                    *reinterpret_cast<ushort2*>(&DH[(long long)(m + 8) * 256 + ng]) = h2;
                    *reinterpret_cast<ushort2*>(&DL[(long long)(m + 8) * 256 + ng]) = l2;
                }
        } else {
            // V: transpose through smem -> g_vth/g_vtl [b][d][sq]
            float* Cs = reinterpret_cast<float*>(sm);      // [128][260]
#pragma unroll
            for (int mt = 0; mt < 4; mt++)
#pragma unroll
                for (int nt = 0; nt < 8; nt++) {
                    int ml = wm * 64 + mt * 16 + (lane >> 2);
                    int nl = wn * 64 + nt * 8 + (lane & 3) * 2;
                    float b0 = bias[nl], b1 = bias[nl + 1];
                    float* a = acc[mt][nt];
                    *reinterpret_cast<float2*>(&Cs[ml * 260 + nl])
                        = make_float2(a[0] + b0, a[1] + b1);
                    *reinterpret_cast<float2*>(&Cs[(ml + 8) * 260 + nl])
                        = make_float2(a[2] + b0, a[3] + b1);
                }
            __syncthreads();
            int nl = tid;                                  // one d-column per thread
            long long bb = m0 >> 12;
            int sq0 = m0 & 4095;
            long long obase = bb * (long long)DIM * SEQ + (long long)nl * SEQ + sq0;
#pragma unroll
            for (int j = 0; j < 32; j++) {
                int ml = j * 4;
                ushort4 hh, ll;
                split_bf(Cs[(ml + 0) * 260 + nl], hh.x, ll.x);
                split_bf(Cs[(ml + 1) * 260 + nl], hh.y, ll.y);
                split_bf(Cs[(ml + 2) * 260 + nl], hh.z, ll.z);
                split_bf(Cs[(ml + 3) * 260 + nl], hh.w, ll.w);
                *reinterpret_cast<ushort4*>(&g_vth[obase + ml]) = hh;
                *reinterpret_cast<ushort4*>(&g_vtl[obase + ml]) = ll;
            }
        }
    } else if (CFG == 1) {
        long long base = (long long)z * SEQ * SEQ;
#pragma unroll
        for (int mt = 0; mt < 4; mt++)
#pragma unroll
            for (int nt = 0; nt < 8; nt++) {
                int m = m0 + wm * 64 + mt * 16 + (lane >> 2);
                int n = n0 + wn * 64 + nt * 8 + (lane & 3) * 2;
                float* a = acc[mt][nt];
                *reinterpret_cast<float2*>(&g_S[base + (long long)m * 4096 + n])
                    = make_float2(a[0], a[1]);
                *reinterpret_cast<float2*>(&g_S[base + (long long)(m + 8) * 4096 + n])
                    = make_float2(a[2], a[3]);
            }
    } else {
#pragma unroll
        for (int mt = 0; mt < 4; mt++)
#pragma unroll
            for (int nt = 0; nt < 8; nt++) {
                int m = m0 + wm * 64 + mt * 16 + (lane >> 2);
                int n = wn * 64 + nt * 8 + (lane & 3) * 2;
                float* a = acc[mt][nt];
                long long rb = ((long long)z * SEQ + m) * 256 + n;
                *reinterpret_cast<float2*>(&out[rb])        = make_float2(a[0], a[1]);
                *reinterpret_cast<float2*>(&out[rb + 2048]) = make_float2(a[2], a[3]);
            }
    }
}

// ---------------------------------------------------------------------------
// merged weight split: Wq/Wk/Wv -> g_wh/g_wl
// ---------------------------------------------------------------------------
__global__ __launch_bounds__(256) void split_w_kernel(
    const float* __restrict__ Wq, const float* __restrict__ Wk,
    const float* __restrict__ Wv)
{
    int gi = blockIdx.x * 256 + threadIdx.x;   // 0..49151 (3 * 16384 float4)
    int wsel = gi >> 14;
    int i = gi & 16383;
    const float* x = (wsel == 0) ? Wq : (wsel == 1) ? Wk : Wv;
    float4 v = reinterpret_cast<const float4*>(x)[i];
    ushort4 hh, ll;
    split_bf(v.x, hh.x, ll.x);
    split_bf(v.y, hh.y, ll.y);
    split_bf(v.z, hh.z, ll.z);
    split_bf(v.w, hh.w, ll.w);
    reinterpret_cast<ushort4*>(g_wh[wsel])[i] = hh;
    reinterpret_cast<ushort4*>(g_wl[wsel])[i] = ll;
}

// ---------------------------------------------------------------------------
// softmax over rows of 4096 in g_S, IN PLACE: fp32 row -> hi bf16 (first
// 8KB) + lo bf16 (second 8KB) of normalized P.  (83% HBM roofline.)
// ---------------------------------------------------------------------------
__global__ __launch_bounds__(256, 1) void softmax_kernel()
{
    __shared__ float red[8];
    const int tid = threadIdx.x;
    const int w = tid >> 5, lane = tid & 31;
    float* S = g_S + (long long)blockIdx.x * 4096;

    float4 x[4];
#pragma unroll
    for (int j = 0; j < 4; j++)
        x[j] = *reinterpret_cast<const float4*>(S + (j * 256 + tid) * 4);

    float mx = -1e30f;
#pragma unroll
    for (int j = 0; j < 4; j++)
        mx = fmaxf(mx, fmaxf(fmaxf(x[j].x, x[j].y), fmaxf(x[j].z, x[j].w)));
#pragma unroll
    for (int o = 16; o; o >>= 1) mx = fmaxf(mx, __shfl_xor_sync(~0u, mx, o));
    if (lane == 0) red[w] = mx;
    __syncthreads();
    mx = red[0];
#pragma unroll
    for (int i = 1; i < 8; i++) mx = fmaxf(mx, red[i]);
    __syncthreads();

    float p[16];
    float sum = 0.f;
#pragma unroll
    for (int j = 0; j < 4; j++) {
        p[4 * j + 0] = __expf(x[j].x - mx);
        p[4 * j + 1] = __expf(x[j].y - mx);
        p[4 * j + 2] = __expf(x[j].z - mx);
        p[4 * j + 3] = __expf(x[j].w - mx);
        sum += (p[4 * j] + p[4 * j + 1]) + (p[4 * j + 2] + p[4 * j + 3]);
    }
#pragma unroll
    for (int o = 16; o; o >>= 1) sum += __shfl_xor_sync(~0u, sum, o);
    if (lane == 0) red[w] = sum;
    __syncthreads();
    sum = 0.f;
#pragma unroll
    for (int i = 0; i < 8; i++) sum += red[i];
    float inv = 1.f / sum;
    __syncthreads();   // all reads done; safe to overwrite row

    unsigned short* Ph = reinterpret_cast<unsigned short*>(S);
    unsigned short* Pl = Ph + 4096;
#pragma unroll
    for (int j = 0; j < 4; j++) {
        ushort4 hh, ll;
        split_bf(p[4 * j + 0] * inv, hh.x, ll.x);
        split_bf(p[4 * j + 1] * inv, hh.y, ll.y);
        split_bf(p[4 * j + 2] * inv, hh.z, ll.z);
        split_bf(p[4 * j + 3] * inv, hh.w, ll.w);
        int o = (j * 256 + tid) * 4;
        *reinterpret_cast<ushort4*>(Ph + o) = hh;
        *reinterpret_cast<ushort4*>(Pl + o) = ll;
    }
}

// ---------------------------------------------------------------------------
extern "C" void kernel_launch(void* const* d_in, const int* in_sizes, int n_in,
                              void* d_out, int out_size)
{
    (void)in_sizes; (void)n_in; (void)out_size;
    const float* query  = (const float*)d_in[0];
    const float* keys   = (const float*)d_in[1];
    const float* values = (const float*)d_in[2];
    const float* Wq     = (const float*)d_in[3];
    const float* bq     = (const float*)d_in[4];
    const float* Wk     = (const float*)d_in[5];
    const float* bk     = (const float*)d_in[6];
    const float* Wv     = (const float*)d_in[7];
    const float* bv     = (const float*)d_in[8];
    float* out = (float*)d_out;

    cudaFuncSetAttribute(gemm_kernel<0>, cudaFuncAttributeMaxDynamicSharedMemorySize, SMEM_TOTAL);
    cudaFuncSetAttribute(gemm_kernel<1>, cudaFuncAttributeMaxDynamicSharedMemorySize, SMEM_TOTAL);
    cudaFuncSetAttribute(gemm_kernel<2>, cudaFuncAttributeMaxDynamicSharedMemorySize, SMEM_TOTAL);

    // 1) weight splits (one launch)
    split_w_kernel<<<192, 256>>>(Wq, Wk, Wv);

    // 2) all three projections (one launch; z selects q/k/v), N=256 per tile
    gemm_kernel<0><<<dim3(NTOK / 128, 1, 3), 256, SMEM_TOTAL>>>(
        query, keys, values, bq, bk, bv, nullptr);

    // 3) scores, all batches
    gemm_kernel<1><<<dim3(SEQ / 128, SEQ / 256, NBATCH), 256, SMEM_TOTAL>>>(
        nullptr, nullptr, nullptr, nullptr, nullptr, nullptr, nullptr);

    // 4) softmax, in place
    softmax_kernel<<<NTOK, 256>>>();

    // 5) context (N=256 in one tile)
    gemm_kernel<2><<<dim3(SEQ / 128, 1, NBATCH), 256, SMEM_TOTAL>>>(
        nullptr, nullptr, nullptr, nullptr, nullptr, nullptr, out);
}

// round 10
// speedup vs baseline: 1.1660x; 1.1660x over previous
#include <cuda_runtime.h>
#include <cuda_fp16.h>
#include <stdint.h>

#define NBATCH 8
#define SEQ    4096
#define DIM    256
#define NTOK   (NBATCH * SEQ)                 // 32768
#define PROJ_ELEMS (NTOK * DIM)               // 8388608
#define S_ELEMS ((long long)NBATCH * SEQ * SEQ)

// ---------------- scratch (static device arrays) ---------------------------
// g_S: fp32 scores; softmax overwrites each 4096-float row in place with
// 4096 fp16 P values (first 8KB of the 16KB row).
__device__ __align__(16) float          g_S[S_ELEMS];                 // 537 MB
__device__ __align__(16) unsigned short g_wh[3][DIM * DIM];
__device__ __align__(16) unsigned short g_wl[3][DIM * DIM];
__device__ __align__(16) unsigned short g_qh[PROJ_ELEMS], g_ql[PROJ_ELEMS];
__device__ __align__(16) unsigned short g_kh[PROJ_ELEMS], g_kl[PROJ_ELEMS];
__device__ __align__(16) unsigned short g_vth[PROJ_ELEMS], g_vtl[PROJ_ELEMS];

// ---------------- helpers ---------------------------------------------------
__device__ __forceinline__ uint32_t smem_u32(const void* p) {
    uint32_t a;
    asm("{ .reg .u64 t; cvta.to.shared.u64 t, %1; cvt.u32.u64 %0, t; }"
        : "=r"(a) : "l"(p));
    return a;
}

#define CP16(dst, src) \
    asm volatile("cp.async.cg.shared.global [%0], [%1], 16;" \
                 :: "r"(dst), "l"(src) : "memory")
#define CP_COMMIT()  asm volatile("cp.async.commit_group;" ::: "memory")
#define CP_WAIT1()   asm volatile("cp.async.wait_group 1;" ::: "memory")
#define CP_WAIT0()   asm volatile("cp.async.wait_group 0;" ::: "memory")

#define LDSM4(r, addr) \
    asm volatile("ldmatrix.sync.aligned.m8n8.x4.shared.b16 {%0,%1,%2,%3}, [%4];" \
                 : "=r"((r)[0]), "=r"((r)[1]), "=r"((r)[2]), "=r"((r)[3]) \
                 : "r"(addr))

// fp16 MMA, fp32 accumulate
#define MMA(d, a, b) \
    asm volatile("mma.sync.aligned.m16n8k16.row.col.f32.f16.f16.f32 " \
                 "{%0,%1,%2,%3},{%4,%5,%6,%7},{%8,%9},{%0,%1,%2,%3};" \
                 : "+f"((d)[0]), "+f"((d)[1]), "+f"((d)[2]), "+f"((d)[3]) \
                 : "r"((a)[0]), "r"((a)[1]), "r"((a)[2]), "r"((a)[3]), \
                   "r"((b)[0]), "r"((b)[1]))

// fp32 -> fp16 hi/lo split (hi = rn(x), lo = rn(x - hi)); 22-bit coverage
__device__ __forceinline__ void split_h(float x, unsigned short& h, unsigned short& l) {
    __half hb = __float2half_rn(x);
    float r = x - __half2float(hb);
    __half lb = __float2half_rn(r);
    h = __half_as_ushort(hb);
    l = __half_as_ushort(lb);
}

// smem: per-stage A (up to 2 splits x 128 rows x 64 fp16 = 128B rows,
// XOR-swizzled) and B (2 splits x 256 rows x 64 fp16).
#define A_SP        16384                 // 128 * 128B
#define B_SP        32768                 // 256 * 128B
#define STAGE_BYTES (2 * A_SP + 2 * B_SP) // 98304
#define SMEM_TOTAL  (2 * STAGE_BYTES)     // 196608
#define SWB(kbyte, r) ((kbyte) ^ (((r) & 7) << 4))

// ---------------------------------------------------------------------------
// Split-fp16 mma.sync GEMM. Block tile 128x256, 256 threads (8 warps, 2x4,
// warp tile 64x64), K chunks of 64, 2-stage cp.async double buffer.
//   CFG 0 (proj):   z selects q/k/v. A = fp32 input (split in staging),
//                   B = g_wh/g_wl[z], K=256. 3 MMAs/product. Epilogue: +bias
//                   -> z<2: split to g_qh/g_ql | g_kh/g_kl;
//                   z=2: transpose via smem -> g_vth/g_vtl [b][d][sq].
//   CFG 1 (scores): A=q, B=k (batch z), K=256, 3 MMAs/product, fp32 -> g_S.
//   CFG 2 (ctx):    A = single-fp16 P rows in g_S (row stride 8192 ushorts),
//                   B = vt hi/lo, K=4096, 2 MMAs/product (P*Vh + P*Vl),
//                   fp32 -> out.
// ---------------------------------------------------------------------------
template<int CFG>
__global__ __launch_bounds__(256, 1)
void gemm_kernel(const float* __restrict__ in_q, const float* __restrict__ in_k,
                 const float* __restrict__ in_v,
                 const float* __restrict__ bq, const float* __restrict__ bk,
                 const float* __restrict__ bv, float* __restrict__ out)
{
    constexpr int K      = (CFG == 2) ? 4096 : 256;
    constexpr int NC     = K / 64;
    constexpr int NCOMBO = (CFG == 2) ? 2 : 3;   // ctx: P*Vh + P*Vl only
    constexpr bool A2    = (CFG != 2);           // A has lo split?
    constexpr long long LDA = (CFG == 2) ? 8192 : 256;
    constexpr long long LDB = (CFG == 2) ? 4096 : 256;

    extern __shared__ __align__(128) char sm[];
    const uint32_t smb = smem_u32(sm);
    const int tid = threadIdx.x;
    const int w = tid >> 5, lane = tid & 31;
    const int wm = w & 1, wn = w >> 1;          // 2 x 4 warp grid
    const int m0 = blockIdx.x * 128, n0 = blockIdx.y * 256;
    const int z = blockIdx.z;

    const float* Afp = nullptr;
    const unsigned short *sp0 = nullptr, *sp1 = nullptr, *sp2 = nullptr, *sp3 = nullptr;
    if (CFG == 0) {
        Afp = (z == 0 ? in_q : z == 1 ? in_k : in_v) + (long long)m0 * 256;
        sp2 = g_wh[z];
        sp3 = g_wl[z];
    } else if (CFG == 1) {
        long long b = z;
        sp0 = g_qh + (b * SEQ + m0) * 256;
        sp1 = g_ql + (b * SEQ + m0) * 256;
        sp2 = g_kh + (b * SEQ + n0) * 256;
        sp3 = g_kl + (b * SEQ + n0) * 256;
    } else {
        long long b = z;
        sp0 = reinterpret_cast<const unsigned short*>(g_S)
              + b * SEQ * 8192 + (long long)m0 * 8192;   // P fp16, row 16KB
        sp2 = g_vth + b * (long long)DIM * SEQ;
        sp3 = g_vtl + b * (long long)DIM * SEQ;
    }

    float acc[4][8][4] = {};    // [mt 16-rows][nt 8-cols][frag]

    auto stage = [&](int c) {
        const int buf = c & 1;
        const uint32_t sb = smb + buf * STAGE_BYTES;
        char* sbp = sm + buf * STAGE_BYTES;
        const int k0 = c * 64;
        if (CFG == 0) {
            // A fp32 -> hi/lo fp16 split in registers, STS
#pragma unroll
            for (int t = tid; t < 2048; t += 256) {
                int r = t >> 4, kq = (t & 15) * 4;       // 128 rows x 16 float4
                float4 v = *reinterpret_cast<const float4*>(Afp + r * 256 + k0 + kq);
                ushort4 hh, ll;
                split_h(v.x, hh.x, ll.x); split_h(v.y, hh.y, ll.y);
                split_h(v.z, hh.z, ll.z); split_h(v.w, hh.w, ll.w);
                int off = r * 128 + SWB(kq * 2, r);
                *reinterpret_cast<ushort4*>(sbp + off)        = hh;
                *reinterpret_cast<ushort4*>(sbp + A_SP + off) = ll;
            }
        } else if (CFG == 1) {
#pragma unroll
            for (int t = tid; t < 2048; t += 256) {
                int sp = t >> 10, r = (t >> 3) & 127, kc = (t & 7) * 8;
                const unsigned short* src = (sp ? sp1 : sp0) + (long long)r * LDA + k0 + kc;
                CP16(sb + sp * A_SP + r * 128 + SWB(kc * 2, r), src);
            }
        } else {
            // ctx: single-split A (fp16 P)
#pragma unroll
            for (int t = tid; t < 1024; t += 256) {
                int r = t >> 3, kc = (t & 7) * 8;
                const unsigned short* src = sp0 + (long long)r * LDA + k0 + kc;
                CP16(sb + r * 128 + SWB(kc * 2, r), src);
            }
        }
#pragma unroll
        for (int t = tid; t < 4096; t += 256) {
            int sp = t >> 11, r = (t >> 3) & 255, kc = (t & 7) * 8;
            const unsigned short* src = (sp ? sp3 : sp2) + (long long)r * LDB + k0 + kc;
            CP16(sb + 2 * A_SP + sp * B_SP + r * 128 + SWB(kc * 2, r), src);
        }
        CP_COMMIT();
    };

    // ldmatrix per-thread constants
    const int a_r0 = wm * 64 + (lane & 7) + ((lane >> 3) & 1) * 8;   // + mt*16
    const int a_kb = (lane >> 4) * 16;
    const int b_n0 = wn * 64 + (lane & 7) + (lane >> 4) * 8;          // + g*16
    const int b_kb = ((lane >> 3) & 1) * 16;

    auto compute = [&](int buf) {
        const uint32_t sa = smb + buf * STAGE_BYTES;
        const uint32_t sbb = sa + 2 * A_SP;
#pragma unroll
        for (int ks = 0; ks < 4; ks++) {
            uint32_t Ahf[4][4], Alf[4][4];
#pragma unroll
            for (int mt = 0; mt < 4; mt++) {
                int row = a_r0 + mt * 16;
                uint32_t ad = sa + row * 128 + SWB(ks * 32 + a_kb, row);
                LDSM4(Ahf[mt], ad);
                if (A2) LDSM4(Alf[mt], ad + A_SP);
            }
#pragma unroll
            for (int g = 0; g < 4; g++) {
                int nrow = b_n0 + g * 16;
                uint32_t bd = sbb + nrow * 128 + SWB(ks * 32 + b_kb, nrow);
                uint32_t Bh[4], Bl[4];
                LDSM4(Bh, bd);
                LDSM4(Bl, bd + B_SP);
#pragma unroll
                for (int combo = 0; combo < NCOMBO; combo++)
#pragma unroll
                    for (int mt = 0; mt < 4; mt++)
#pragma unroll
                        for (int sub = 0; sub < 2; sub++) {
                            int nt = g * 2 + sub;
                            const uint32_t* af =
                                (combo == 2) ? Alf[mt] : Ahf[mt];
                            const uint32_t* bf =
                                (combo == 1) ? (Bl + sub * 2) : (Bh + sub * 2);
                            MMA(acc[mt][nt], af, bf);
                        }
            }
        }
    };

    stage(0);
    for (int c = 0; c < NC; c++) {
        __syncthreads();                 // prior compute done before buffer reuse
        if (c + 1 < NC) stage(c + 1);
        if (c + 1 < NC) CP_WAIT1(); else CP_WAIT0();
        __syncthreads();
        compute(c & 1);
    }
    __syncthreads();

    // ---------------- epilogue ----------------
    if (CFG == 0) {
        const float* bias = (z == 0) ? bq : (z == 1) ? bk : bv;
        if (z < 2) {
            unsigned short* DH = (z == 0) ? g_qh : g_kh;
            unsigned short* DL = (z == 0) ? g_ql : g_kl;
#pragma unroll
            for (int mt = 0; mt < 4; mt++)
#pragma unroll
                for (int nt = 0; nt < 8; nt++) {
                    int m  = m0 + wm * 64 + mt * 16 + (lane >> 2);
                    int ng = wn * 64 + nt * 8 + (lane & 3) * 2;
                    float b0 = bias[ng], b1 = bias[ng + 1];
                    float* a = acc[mt][nt];
                    ushort2 h2, l2;
                    split_h(a[0] + b0, h2.x, l2.x); split_h(a[1] + b1, h2.y, l2.y);
                    *reinterpret_cast<ushort2*>(&DH[(long long)m * 256 + ng]) = h2;
                    *reinterpret_cast<ushort2*>(&DL[(long long)m * 256 + ng]) = l2;
                    split_h(a[2] + b0, h2.x, l2.x); split_h(a[3] + b1, h2.y, l2.y);
                    *reinterpret_cast<ushort2*>(&DH[(long long)(m + 8) * 256 + ng]) = h2;
                    *reinterpret_cast<ushort2*>(&DL[(long long)(m + 8) * 256 + ng]) = l2;
                }
        } else {
            // V: transpose through smem -> g_vth/g_vtl [b][d][sq]
            float* Cs = reinterpret_cast<float*>(sm);      // [128][260]
#pragma unroll
            for (int mt = 0; mt < 4; mt++)
#pragma unroll
                for (int nt = 0; nt < 8; nt++) {
                    int ml = wm * 64 + mt * 16 + (lane >> 2);
                    int nl = wn * 64 + nt * 8 + (lane & 3) * 2;
                    float b0 = bias[nl], b1 = bias[nl + 1];
                    float* a = acc[mt][nt];
                    *reinterpret_cast<float2*>(&Cs[ml * 260 + nl])
                        = make_float2(a[0] + b0, a[1] + b1);
                    *reinterpret_cast<float2*>(&Cs[(ml + 8) * 260 + nl])
                        = make_float2(a[2] + b0, a[3] + b1);
                }
            __syncthreads();
            int nl = tid;                                  // one d-column per thread
            long long bb = m0 >> 12;
            int sq0 = m0 & 4095;
            long long obase = bb * (long long)DIM * SEQ + (long long)nl * SEQ + sq0;
#pragma unroll
            for (int j = 0; j < 32; j++) {
                int ml = j * 4;
                ushort4 hh, ll;
                split_h(Cs[(ml + 0) * 260 + nl], hh.x, ll.x);
                split_h(Cs[(ml + 1) * 260 + nl], hh.y, ll.y);
                split_h(Cs[(ml + 2) * 260 + nl], hh.z, ll.z);
                split_h(Cs[(ml + 3) * 260 + nl], hh.w, ll.w);
                *reinterpret_cast<ushort4*>(&g_vth[obase + ml]) = hh;
                *reinterpret_cast<ushort4*>(&g_vtl[obase + ml]) = ll;
            }
        }
    } else if (CFG == 1) {
        long long base = (long long)z * SEQ * SEQ;
#pragma unroll
        for (int mt = 0; mt < 4; mt++)
#pragma unroll
            for (int nt = 0; nt < 8; nt++) {
                int m = m0 + wm * 64 + mt * 16 + (lane >> 2);
                int n = n0 + wn * 64 + nt * 8 + (lane & 3) * 2;
                float* a = acc[mt][nt];
                *reinterpret_cast<float2*>(&g_S[base + (long long)m * 4096 + n])
                    = make_float2(a[0], a[1]);
                *reinterpret_cast<float2*>(&g_S[base + (long long)(m + 8) * 4096 + n])
                    = make_float2(a[2], a[3]);
            }
    } else {
#pragma unroll
        for (int mt = 0; mt < 4; mt++)
#pragma unroll
            for (int nt = 0; nt < 8; nt++) {
                int m = m0 + wm * 64 + mt * 16 + (lane >> 2);
                int n = wn * 64 + nt * 8 + (lane & 3) * 2;
                float* a = acc[mt][nt];
                long long rb = ((long long)z * SEQ + m) * 256 + n;
                *reinterpret_cast<float2*>(&out[rb])        = make_float2(a[0], a[1]);
                *reinterpret_cast<float2*>(&out[rb + 2048]) = make_float2(a[2], a[3]);
            }
    }
}

// ---------------------------------------------------------------------------
// merged weight split: Wq/Wk/Wv -> g_wh/g_wl (fp16 hi/lo)
// ---------------------------------------------------------------------------
__global__ __launch_bounds__(256) void split_w_kernel(
    const float* __restrict__ Wq, const float* __restrict__ Wk,
    const float* __restrict__ Wv)
{
    int gi = blockIdx.x * 256 + threadIdx.x;   // 0..49151 (3 * 16384 float4)
    int wsel = gi >> 14;
    int i = gi & 16383;
    const float* x = (wsel == 0) ? Wq : (wsel == 1) ? Wk : Wv;
    float4 v = reinterpret_cast<const float4*>(x)[i];
    ushort4 hh, ll;
    split_h(v.x, hh.x, ll.x);
    split_h(v.y, hh.y, ll.y);
    split_h(v.z, hh.z, ll.z);
    split_h(v.w, hh.w, ll.w);
    reinterpret_cast<ushort4*>(g_wh[wsel])[i] = hh;
    reinterpret_cast<ushort4*>(g_wl[wsel])[i] = ll;
}

// ---------------------------------------------------------------------------
// softmax over rows of 4096 in g_S, IN PLACE: fp32 row -> single fp16 P
// (first 8KB of the row). Row fully read into registers first.
// ---------------------------------------------------------------------------
__global__ __launch_bounds__(256, 1) void softmax_kernel()
{
    __shared__ float red[8];
    const int tid = threadIdx.x;
    const int w = tid >> 5, lane = tid & 31;
    float* S = g_S + (long long)blockIdx.x * 4096;

    float4 x[4];
#pragma unroll
    for (int j = 0; j < 4; j++)
        x[j] = *reinterpret_cast<const float4*>(S + (j * 256 + tid) * 4);

    float mx = -1e30f;
#pragma unroll
    for (int j = 0; j < 4; j++)
        mx = fmaxf(mx, fmaxf(fmaxf(x[j].x, x[j].y), fmaxf(x[j].z, x[j].w)));
#pragma unroll
    for (int o = 16; o; o >>= 1) mx = fmaxf(mx, __shfl_xor_sync(~0u, mx, o));
    if (lane == 0) red[w] = mx;
    __syncthreads();
    mx = red[0];
#pragma unroll
    for (int i = 1; i < 8; i++) mx = fmaxf(mx, red[i]);
    __syncthreads();

    float p[16];
    float sum = 0.f;
#pragma unroll
    for (int j = 0; j < 4; j++) {
        p[4 * j + 0] = __expf(x[j].x - mx);
        p[4 * j + 1] = __expf(x[j].y - mx);
        p[4 * j + 2] = __expf(x[j].z - mx);
        p[4 * j + 3] = __expf(x[j].w - mx);
        sum += (p[4 * j] + p[4 * j + 1]) + (p[4 * j + 2] + p[4 * j + 3]);
    }
#pragma unroll
    for (int o = 16; o; o >>= 1) sum += __shfl_xor_sync(~0u, sum, o);
    if (lane == 0) red[w] = sum;
    __syncthreads();
    sum = 0.f;
#pragma unroll
    for (int i = 0; i < 8; i++) sum += red[i];
    float inv = 1.f / sum;
    __syncthreads();   // all reads done; safe to overwrite row

    unsigned short* Ph = reinterpret_cast<unsigned short*>(S);
#pragma unroll
    for (int j = 0; j < 4; j++) {
        ushort4 hh;
        hh.x = __half_as_ushort(__float2half_rn(p[4 * j + 0] * inv));
        hh.y = __half_as_ushort(__float2half_rn(p[4 * j + 1] * inv));
        hh.z = __half_as_ushort(__float2half_rn(p[4 * j + 2] * inv));
        hh.w = __half_as_ushort(__float2half_rn(p[4 * j + 3] * inv));
        *reinterpret_cast<ushort4*>(Ph + (j * 256 + tid) * 4) = hh;
    }
}

// ---------------------------------------------------------------------------
extern "C" void kernel_launch(void* const* d_in, const int* in_sizes, int n_in,
                              void* d_out, int out_size)
{
    (void)in_sizes; (void)n_in; (void)out_size;
    const float* query  = (const float*)d_in[0];
    const float* keys   = (const float*)d_in[1];
    const float* values = (const float*)d_in[2];
    const float* Wq     = (const float*)d_in[3];
    const float* bq     = (const float*)d_in[4];
    const float* Wk     = (const float*)d_in[5];
    const float* bk     = (const float*)d_in[6];
    const float* Wv     = (const float*)d_in[7];
    const float* bv     = (const float*)d_in[8];
    float* out = (float*)d_out;

    cudaFuncSetAttribute(gemm_kernel<0>, cudaFuncAttributeMaxDynamicSharedMemorySize, SMEM_TOTAL);
    cudaFuncSetAttribute(gemm_kernel<1>, cudaFuncAttributeMaxDynamicSharedMemorySize, SMEM_TOTAL);
    cudaFuncSetAttribute(gemm_kernel<2>, cudaFuncAttributeMaxDynamicSharedMemorySize, SMEM_TOTAL);

    // 1) weight splits (one launch)
    split_w_kernel<<<192, 256>>>(Wq, Wk, Wv);

    // 2) all three projections (one launch; z selects q/k/v)
    gemm_kernel<0><<<dim3(NTOK / 128, 1, 3), 256, SMEM_TOTAL>>>(
        query, keys, values, bq, bk, bv, nullptr);

    // 3) scores, all batches
    gemm_kernel<1><<<dim3(SEQ / 128, SEQ / 256, NBATCH), 256, SMEM_TOTAL>>>(
        nullptr, nullptr, nullptr, nullptr, nullptr, nullptr, nullptr);

    // 4) softmax, in place (fp32 row -> single fp16 P)
    softmax_kernel<<<NTOK, 256>>>();

    // 5) context (2 MMAs/product)
    gemm_kernel<2><<<dim3(SEQ / 128, 1, NBATCH), 256, SMEM_TOTAL>>>(
        nullptr, nullptr, nullptr, nullptr, nullptr, nullptr, out);
}

// round 11
// speedup vs baseline: 1.3584x; 1.1649x over previous
#include <cuda_runtime.h>
#include <cuda_fp16.h>
#include <stdint.h>

#define NBATCH 8
#define SEQ    4096
#define DIM    256
#define NTOK   (NBATCH * SEQ)                 // 32768
#define PROJ_ELEMS (NTOK * DIM)               // 8388608
#define S_ELEMS ((long long)NBATCH * SEQ * SEQ)

// ---------------- scratch (static device arrays) ---------------------------
// g_S: fp32 scores; softmax overwrites each 4096-float row in place with
// 4096 fp16 P values (first 8KB of the 16KB row).
__device__ __align__(16) float          g_S[S_ELEMS];                 // 537 MB
__device__ __align__(16) unsigned short g_wh[3][DIM * DIM];
__device__ __align__(16) unsigned short g_wl[3][DIM * DIM];
__device__ __align__(16) unsigned short g_qh[PROJ_ELEMS], g_ql[PROJ_ELEMS];
__device__ __align__(16) unsigned short g_kh[PROJ_ELEMS], g_kl[PROJ_ELEMS];
__device__ __align__(16) unsigned short g_vth[PROJ_ELEMS];   // V^T hi only

// ---------------- helpers ---------------------------------------------------
__device__ __forceinline__ uint32_t smem_u32(const void* p) {
    uint32_t a;
    asm("{ .reg .u64 t; cvta.to.shared.u64 t, %1; cvt.u32.u64 %0, t; }"
        : "=r"(a) : "l"(p));
    return a;
}

#define CP16(dst, src) \
    asm volatile("cp.async.cg.shared.global [%0], [%1], 16;" \
                 :: "r"(dst), "l"(src) : "memory")
#define CP_COMMIT()  asm volatile("cp.async.commit_group;" ::: "memory")
#define CP_WAIT1()   asm volatile("cp.async.wait_group 1;" ::: "memory")
#define CP_WAIT0()   asm volatile("cp.async.wait_group 0;" ::: "memory")

#define LDSM4(r, addr) \
    asm volatile("ldmatrix.sync.aligned.m8n8.x4.shared.b16 {%0,%1,%2,%3}, [%4];" \
                 : "=r"((r)[0]), "=r"((r)[1]), "=r"((r)[2]), "=r"((r)[3]) \
                 : "r"(addr))

// fp16 MMA, fp32 accumulate
#define MMA(d, a, b) \
    asm volatile("mma.sync.aligned.m16n8k16.row.col.f32.f16.f16.f32 " \
                 "{%0,%1,%2,%3},{%4,%5,%6,%7},{%8,%9},{%0,%1,%2,%3};" \
                 : "+f"((d)[0]), "+f"((d)[1]), "+f"((d)[2]), "+f"((d)[3]) \
                 : "r"((a)[0]), "r"((a)[1]), "r"((a)[2]), "r"((a)[3]), \
                   "r"((b)[0]), "r"((b)[1]))

// fp32 -> fp16 hi/lo split (hi = rn(x), lo = rn(x - hi)); 22-bit coverage
__device__ __forceinline__ void split_h(float x, unsigned short& h, unsigned short& l) {
    __half hb = __float2half_rn(x);
    float r = x - __half2float(hb);
    __half lb = __float2half_rn(r);
    h = __half_as_ushort(hb);
    l = __half_as_ushort(lb);
}

// smem: per-stage A (up to 2 splits x 128 rows x 64 fp16 = 128B rows,
// XOR-swizzled) and B (up to 2 splits x 256 rows x 64 fp16).
#define A_SP        16384                 // 128 * 128B
#define B_SP        32768                 // 256 * 128B
#define STAGE_BYTES (2 * A_SP + 2 * B_SP) // 98304
#define SMEM_TOTAL  (2 * STAGE_BYTES)     // 196608
#define SWB(kbyte, r) ((kbyte) ^ (((r) & 7) << 4))

// ---------------------------------------------------------------------------
// Split-fp16 mma.sync GEMM. Block tile 128x256, 256 threads (8 warps, 2x4,
// warp tile 64x64), K chunks of 64, 2-stage cp.async double buffer.
//   CFG 0 (proj):   z selects q/k/v. A = fp32 input (split in staging),
//                   B = g_wh/g_wl[z], K=256. 3 MMAs/product. Epilogue: +bias
//                   -> z<2: split to g_qh/g_ql | g_kh/g_kl;
//                   z=2: transpose via smem -> g_vth (hi only) [b][d][sq].
//   CFG 1 (scores): A=q, B=k (batch z), K=256, 3 MMAs/product, fp32 -> g_S.
//   CFG 2 (ctx):    A = single-fp16 P rows in g_S (row stride 8192 ushorts),
//                   B = vt hi only, K=4096, 1 MMA/product, fp32 -> out.
// ---------------------------------------------------------------------------
template<int CFG>
__global__ __launch_bounds__(256, 1)
void gemm_kernel(const float* __restrict__ in_q, const float* __restrict__ in_k,
                 const float* __restrict__ in_v,
                 const float* __restrict__ bq, const float* __restrict__ bk,
                 const float* __restrict__ bv, float* __restrict__ out)
{
    constexpr int K      = (CFG == 2) ? 4096 : 256;
    constexpr int NC     = K / 64;
    constexpr int NCOMBO = (CFG == 2) ? 1 : 3;   // ctx: P*Vh only
    constexpr bool A2    = (CFG != 2);           // A has lo split?
    constexpr bool B2    = (CFG != 2);           // B has lo split?
    constexpr long long LDA = (CFG == 2) ? 8192 : 256;
    constexpr long long LDB = (CFG == 2) ? 4096 : 256;

    extern __shared__ __align__(128) char sm[];
    const uint32_t smb = smem_u32(sm);
    const int tid = threadIdx.x;
    const int w = tid >> 5, lane = tid & 31;
    const int wm = w & 1, wn = w >> 1;          // 2 x 4 warp grid
    const int m0 = blockIdx.x * 128, n0 = blockIdx.y * 256;
    const int z = blockIdx.z;

    const float* Afp = nullptr;
    const unsigned short *sp0 = nullptr, *sp1 = nullptr, *sp2 = nullptr, *sp3 = nullptr;
    if (CFG == 0) {
        Afp = (z == 0 ? in_q : z == 1 ? in_k : in_v) + (long long)m0 * 256;
        sp2 = g_wh[z];
        sp3 = g_wl[z];
    } else if (CFG == 1) {
        long long b = z;
        sp0 = g_qh + (b * SEQ + m0) * 256;
        sp1 = g_ql + (b * SEQ + m0) * 256;
        sp2 = g_kh + (b * SEQ + n0) * 256;
        sp3 = g_kl + (b * SEQ + n0) * 256;
    } else {
        long long b = z;
        sp0 = reinterpret_cast<const unsigned short*>(g_S)
              + b * SEQ * 8192 + (long long)m0 * 8192;   // P fp16, row 16KB
        sp2 = g_vth + b * (long long)DIM * SEQ;
    }

    float acc[4][8][4] = {};    // [mt 16-rows][nt 8-cols][frag]

    auto stage = [&](int c) {
        const int buf = c & 1;
        const uint32_t sb = smb + buf * STAGE_BYTES;
        char* sbp = sm + buf * STAGE_BYTES;
        const int k0 = c * 64;
        if (CFG == 0) {
            // A fp32 -> hi/lo fp16 split in registers, STS
#pragma unroll
            for (int t = tid; t < 2048; t += 256) {
                int r = t >> 4, kq = (t & 15) * 4;       // 128 rows x 16 float4
                float4 v = *reinterpret_cast<const float4*>(Afp + r * 256 + k0 + kq);
                ushort4 hh, ll;
                split_h(v.x, hh.x, ll.x); split_h(v.y, hh.y, ll.y);
                split_h(v.z, hh.z, ll.z); split_h(v.w, hh.w, ll.w);
                int off = r * 128 + SWB(kq * 2, r);
                *reinterpret_cast<ushort4*>(sbp + off)        = hh;
                *reinterpret_cast<ushort4*>(sbp + A_SP + off) = ll;
            }
        } else if (CFG == 1) {
#pragma unroll
            for (int t = tid; t < 2048; t += 256) {
                int sp = t >> 10, r = (t >> 3) & 127, kc = (t & 7) * 8;
                const unsigned short* src = (sp ? sp1 : sp0) + (long long)r * LDA + k0 + kc;
                CP16(sb + sp * A_SP + r * 128 + SWB(kc * 2, r), src);
            }
        } else {
            // ctx: single-split A (fp16 P)
#pragma unroll
            for (int t = tid; t < 1024; t += 256) {
                int r = t >> 3, kc = (t & 7) * 8;
                const unsigned short* src = sp0 + (long long)r * LDA + k0 + kc;
                CP16(sb + r * 128 + SWB(kc * 2, r), src);
            }
        }
        if (B2) {
#pragma unroll
            for (int t = tid; t < 4096; t += 256) {
                int sp = t >> 11, r = (t >> 3) & 255, kc = (t & 7) * 8;
                const unsigned short* src = (sp ? sp3 : sp2) + (long long)r * LDB + k0 + kc;
                CP16(sb + 2 * A_SP + sp * B_SP + r * 128 + SWB(kc * 2, r), src);
            }
        } else {
#pragma unroll
            for (int t = tid; t < 2048; t += 256) {
                int r = t >> 3, kc = (t & 7) * 8;
                const unsigned short* src = sp2 + (long long)r * LDB + k0 + kc;
                CP16(sb + 2 * A_SP + r * 128 + SWB(kc * 2, r), src);
            }
        }
        CP_COMMIT();
    };

    // ldmatrix per-thread constants
    const int a_r0 = wm * 64 + (lane & 7) + ((lane >> 3) & 1) * 8;   // + mt*16
    const int a_kb = (lane >> 4) * 16;
    const int b_n0 = wn * 64 + (lane & 7) + (lane >> 4) * 8;          // + g*16
    const int b_kb = ((lane >> 3) & 1) * 16;

    auto compute = [&](int buf) {
        const uint32_t sa = smb + buf * STAGE_BYTES;
        const uint32_t sbb = sa + 2 * A_SP;
#pragma unroll
        for (int ks = 0; ks < 4; ks++) {
            uint32_t Ahf[4][4], Alf[4][4];
#pragma unroll
            for (int mt = 0; mt < 4; mt++) {
                int row = a_r0 + mt * 16;
                uint32_t ad = sa + row * 128 + SWB(ks * 32 + a_kb, row);
                LDSM4(Ahf[mt], ad);
                if (A2) LDSM4(Alf[mt], ad + A_SP);
            }
#pragma unroll
            for (int g = 0; g < 4; g++) {
                int nrow = b_n0 + g * 16;
                uint32_t bd = sbb + nrow * 128 + SWB(ks * 32 + b_kb, nrow);
                uint32_t Bh[4], Bl[4];
                LDSM4(Bh, bd);
                if (B2) LDSM4(Bl, bd + B_SP);
#pragma unroll
                for (int combo = 0; combo < NCOMBO; combo++)
#pragma unroll
                    for (int mt = 0; mt < 4; mt++)
#pragma unroll
                        for (int sub = 0; sub < 2; sub++) {
                            int nt = g * 2 + sub;
                            const uint32_t* af =
                                (combo == 2) ? Alf[mt] : Ahf[mt];
                            const uint32_t* bf =
                                (combo == 1) ? (Bl + sub * 2) : (Bh + sub * 2);
                            MMA(acc[mt][nt], af, bf);
                        }
            }
        }
    };

    stage(0);
    for (int c = 0; c < NC; c++) {
        __syncthreads();                 // prior compute done before buffer reuse
        if (c + 1 < NC) stage(c + 1);
        if (c + 1 < NC) CP_WAIT1(); else CP_WAIT0();
        __syncthreads();
        compute(c & 1);
    }
    __syncthreads();

    // ---------------- epilogue ----------------
    if (CFG == 0) {
        const float* bias = (z == 0) ? bq : (z == 1) ? bk : bv;
        if (z < 2) {
            unsigned short* DH = (z == 0) ? g_qh : g_kh;
            unsigned short* DL = (z == 0) ? g_ql : g_kl;
#pragma unroll
            for (int mt = 0; mt < 4; mt++)
#pragma unroll
                for (int nt = 0; nt < 8; nt++) {
                    int m  = m0 + wm * 64 + mt * 16 + (lane >> 2);
                    int ng = wn * 64 + nt * 8 + (lane & 3) * 2;
                    float b0 = bias[ng], b1 = bias[ng + 1];
                    float* a = acc[mt][nt];
                    ushort2 h2, l2;
                    split_h(a[0] + b0, h2.x, l2.x); split_h(a[1] + b1, h2.y, l2.y);
                    *reinterpret_cast<ushort2*>(&DH[(long long)m * 256 + ng]) = h2;
                    *reinterpret_cast<ushort2*>(&DL[(long long)m * 256 + ng]) = l2;
                    split_h(a[2] + b0, h2.x, l2.x); split_h(a[3] + b1, h2.y, l2.y);
                    *reinterpret_cast<ushort2*>(&DH[(long long)(m + 8) * 256 + ng]) = h2;
                    *reinterpret_cast<ushort2*>(&DL[(long long)(m + 8) * 256 + ng]) = l2;
                }
        } else {
            // V: transpose through smem -> g_vth (hi only) [b][d][sq]
            float* Cs = reinterpret_cast<float*>(sm);      // [128][260]
#pragma unroll
            for (int mt = 0; mt < 4; mt++)
#pragma unroll
                for (int nt = 0; nt < 8; nt++) {
                    int ml = wm * 64 + mt * 16 + (lane >> 2);
                    int nl = wn * 64 + nt * 8 + (lane & 3) * 2;
                    float b0 = bias[nl], b1 = bias[nl + 1];
                    float* a = acc[mt][nt];
                    *reinterpret_cast<float2*>(&Cs[ml * 260 + nl])
                        = make_float2(a[0] + b0, a[1] + b1);
                    *reinterpret_cast<float2*>(&Cs[(ml + 8) * 260 + nl])
                        = make_float2(a[2] + b0, a[3] + b1);
                }
            __syncthreads();
            int nl = tid;                                  // one d-column per thread
            long long bb = m0 >> 12;
            int sq0 = m0 & 4095;
            long long obase = bb * (long long)DIM * SEQ + (long long)nl * SEQ + sq0;
#pragma unroll
            for (int j = 0; j < 32; j++) {
                int ml = j * 4;
                ushort4 hh;
                hh.x = __half_as_ushort(__float2half_rn(Cs[(ml + 0) * 260 + nl]));
                hh.y = __half_as_ushort(__float2half_rn(Cs[(ml + 1) * 260 + nl]));
                hh.z = __half_as_ushort(__float2half_rn(Cs[(ml + 2) * 260 + nl]));
                hh.w = __half_as_ushort(__float2half_rn(Cs[(ml + 3) * 260 + nl]));
                *reinterpret_cast<ushort4*>(&g_vth[obase + ml]) = hh;
            }
        }
    } else if (CFG == 1) {
        long long base = (long long)z * SEQ * SEQ;
#pragma unroll
        for (int mt = 0; mt < 4; mt++)
#pragma unroll
            for (int nt = 0; nt < 8; nt++) {
                int m = m0 + wm * 64 + mt * 16 + (lane >> 2);
                int n = n0 + wn * 64 + nt * 8 + (lane & 3) * 2;
                float* a = acc[mt][nt];
                *reinterpret_cast<float2*>(&g_S[base + (long long)m * 4096 + n])
                    = make_float2(a[0], a[1]);
                *reinterpret_cast<float2*>(&g_S[base + (long long)(m + 8) * 4096 + n])
                    = make_float2(a[2], a[3]);
            }
    } else {
#pragma unroll
        for (int mt = 0; mt < 4; mt++)
#pragma unroll
            for (int nt = 0; nt < 8; nt++) {
                int m = m0 + wm * 64 + mt * 16 + (lane >> 2);
                int n = wn * 64 + nt * 8 + (lane & 3) * 2;
                float* a = acc[mt][nt];
                long long rb = ((long long)z * SEQ + m) * 256 + n;
                *reinterpret_cast<float2*>(&out[rb])        = make_float2(a[0], a[1]);
                *reinterpret_cast<float2*>(&out[rb + 2048]) = make_float2(a[2], a[3]);
            }
    }
}

// ---------------------------------------------------------------------------
// merged weight split: Wq/Wk/Wv -> g_wh/g_wl (fp16 hi/lo)
// ---------------------------------------------------------------------------
__global__ __launch_bounds__(256) void split_w_kernel(
    const float* __restrict__ Wq, const float* __restrict__ Wk,
    const float* __restrict__ Wv)
{
    int gi = blockIdx.x * 256 + threadIdx.x;   // 0..49151 (3 * 16384 float4)
    int wsel = gi >> 14;
    int i = gi & 16383;
    const float* x = (wsel == 0) ? Wq : (wsel == 1) ? Wk : Wv;
    float4 v = reinterpret_cast<const float4*>(x)[i];
    ushort4 hh, ll;
    split_h(v.x, hh.x, ll.x);
    split_h(v.y, hh.y, ll.y);
    split_h(v.z, hh.z, ll.z);
    split_h(v.w, hh.w, ll.w);
    reinterpret_cast<ushort4*>(g_wh[wsel])[i] = hh;
    reinterpret_cast<ushort4*>(g_wl[wsel])[i] = ll;
}

// ---------------------------------------------------------------------------
// softmax over rows of 4096 in g_S, IN PLACE: fp32 row -> single fp16 P
// (first 8KB of the row). Row fully read into registers first.
// ---------------------------------------------------------------------------
__global__ __launch_bounds__(256, 1) void softmax_kernel()
{
    __shared__ float red[8];
    const int tid = threadIdx.x;
    const int w = tid >> 5, lane = tid & 31;
    float* S = g_S + (long long)blockIdx.x * 4096;

    float4 x[4];
#pragma unroll
    for (int j = 0; j < 4; j++)
        x[j] = *reinterpret_cast<const float4*>(S + (j * 256 + tid) * 4);

    float mx = -1e30f;
#pragma unroll
    for (int j = 0; j < 4; j++)
        mx = fmaxf(mx, fmaxf(fmaxf(x[j].x, x[j].y), fmaxf(x[j].z, x[j].w)));
#pragma unroll
    for (int o = 16; o; o >>= 1) mx = fmaxf(mx, __shfl_xor_sync(~0u, mx, o));
    if (lane == 0) red[w] = mx;
    __syncthreads();
    mx = red[0];
#pragma unroll
    for (int i = 1; i < 8; i++) mx = fmaxf(mx, red[i]);
    __syncthreads();

    float p[16];
    float sum = 0.f;
#pragma unroll
    for (int j = 0; j < 4; j++) {
        p[4 * j + 0] = __expf(x[j].x - mx);
        p[4 * j + 1] = __expf(x[j].y - mx);
        p[4 * j + 2] = __expf(x[j].z - mx);
        p[4 * j + 3] = __expf(x[j].w - mx);
        sum += (p[4 * j] + p[4 * j + 1]) + (p[4 * j + 2] + p[4 * j + 3]);
    }
#pragma unroll
    for (int o = 16; o; o >>= 1) sum += __shfl_xor_sync(~0u, sum, o);
    if (lane == 0) red[w] = sum;
    __syncthreads();
    sum = 0.f;
#pragma unroll
    for (int i = 0; i < 8; i++) sum += red[i];
    float inv = 1.f / sum;
    __syncthreads();   // all reads done; safe to overwrite row

    unsigned short* Ph = reinterpret_cast<unsigned short*>(S);
#pragma unroll
    for (int j = 0; j < 4; j++) {
        ushort4 hh;
        hh.x = __half_as_ushort(__float2half_rn(p[4 * j + 0] * inv));
        hh.y = __half_as_ushort(__float2half_rn(p[4 * j + 1] * inv));
        hh.z = __half_as_ushort(__float2half_rn(p[4 * j + 2] * inv));
        hh.w = __half_as_ushort(__float2half_rn(p[4 * j + 3] * inv));
        *reinterpret_cast<ushort4*>(Ph + (j * 256 + tid) * 4) = hh;
    }
}

// ---------------------------------------------------------------------------
extern "C" void kernel_launch(void* const* d_in, const int* in_sizes, int n_in,
                              void* d_out, int out_size)
{
    (void)in_sizes; (void)n_in; (void)out_size;
    const float* query  = (const float*)d_in[0];
    const float* keys   = (const float*)d_in[1];
    const float* values = (const float*)d_in[2];
    const float* Wq     = (const float*)d_in[3];
    const float* bq     = (const float*)d_in[4];
    const float* Wk     = (const float*)d_in[5];
    const float* bk     = (const float*)d_in[6];
    const float* Wv     = (const float*)d_in[7];
    const float* bv     = (const float*)d_in[8];
    float* out = (float*)d_out;

    cudaFuncSetAttribute(gemm_kernel<0>, cudaFuncAttributeMaxDynamicSharedMemorySize, SMEM_TOTAL);
    cudaFuncSetAttribute(gemm_kernel<1>, cudaFuncAttributeMaxDynamicSharedMemorySize, SMEM_TOTAL);
    cudaFuncSetAttribute(gemm_kernel<2>, cudaFuncAttributeMaxDynamicSharedMemorySize, SMEM_TOTAL);

    // 1) weight splits (one launch)
    split_w_kernel<<<192, 256>>>(Wq, Wk, Wv);

    // 2) all three projections (one launch; z selects q/k/v)
    gemm_kernel<0><<<dim3(NTOK / 128, 1, 3), 256, SMEM_TOTAL>>>(
        query, keys, values, bq, bk, bv, nullptr);

    // 3) scores, all batches
    gemm_kernel<1><<<dim3(SEQ / 128, SEQ / 256, NBATCH), 256, SMEM_TOTAL>>>(
        nullptr, nullptr, nullptr, nullptr, nullptr, nullptr, nullptr);

    // 4) softmax, in place (fp32 row -> single fp16 P)
    softmax_kernel<<<NTOK, 256>>>();

    // 5) context (1 MMA/product: P fp16 x V_hi fp16)
    gemm_kernel<2><<<dim3(SEQ / 128, 1, NBATCH), 256, SMEM_TOTAL>>>(
        nullptr, nullptr, nullptr, nullptr, nullptr, nullptr, out);
}

// round 13
// speedup vs baseline: 1.4093x; 1.0375x over previous
#include <cuda_runtime.h>
#include <cuda_fp16.h>
#include <stdint.h>

#define NBATCH 8
#define SEQ    4096
#define DIM    256
#define NTOK   (NBATCH * SEQ)                 // 32768
#define PROJ_ELEMS (NTOK * DIM)               // 8388608
#define S_ELEMS ((long long)NBATCH * SEQ * SEQ)

// ---------------- scratch (static device arrays) ---------------------------
// g_S: fp32 scores; softmax overwrites each 4096-float row in place with
// 4096 fp16 P values (first 8KB of the 16KB row).
__device__ __align__(16) float          g_S[S_ELEMS];                 // 537 MB
__device__ __align__(16) unsigned short g_wh[3][DIM * DIM];
__device__ __align__(16) unsigned short g_wl[3][DIM * DIM];
__device__ __align__(16) unsigned short g_qh[PROJ_ELEMS], g_ql[PROJ_ELEMS];
__device__ __align__(16) unsigned short g_kh[PROJ_ELEMS], g_kl[PROJ_ELEMS];
__device__ __align__(16) unsigned short g_vth[PROJ_ELEMS];   // V^T hi only

// ---------------- helpers ---------------------------------------------------
__device__ __forceinline__ uint32_t smem_u32(const void* p) {
    uint32_t a;
    asm("{ .reg .u64 t; cvta.to.shared.u64 t, %1; cvt.u32.u64 %0, t; }"
        : "=r"(a) : "l"(p));
    return a;
}

#define CP16(dst, src) \
    asm volatile("cp.async.cg.shared.global [%0], [%1], 16;" \
                 :: "r"(dst), "l"(src) : "memory")
#define CP_COMMIT()  asm volatile("cp.async.commit_group;" ::: "memory")
#define CP_WAIT1()   asm volatile("cp.async.wait_group 1;" ::: "memory")
#define CP_WAIT0()   asm volatile("cp.async.wait_group 0;" ::: "memory")

#define LDSM4(r, addr) \
    asm volatile("ldmatrix.sync.aligned.m8n8.x4.shared.b16 {%0,%1,%2,%3}, [%4];" \
                 : "=r"((r)[0]), "=r"((r)[1]), "=r"((r)[2]), "=r"((r)[3]) \
                 : "r"(addr))

// fp16 MMA, fp32 accumulate
#define MMA(d, a, b) \
    asm volatile("mma.sync.aligned.m16n8k16.row.col.f32.f16.f16.f32 " \
                 "{%0,%1,%2,%3},{%4,%5,%6,%7},{%8,%9},{%0,%1,%2,%3};" \
                 : "+f"((d)[0]), "+f"((d)[1]), "+f"((d)[2]), "+f"((d)[3]) \
                 : "r"((a)[0]), "r"((a)[1]), "r"((a)[2]), "r"((a)[3]), \
                   "r"((b)[0]), "r"((b)[1]))

// fp32 -> fp16 hi/lo split (hi = rn(x), lo = rn(x - hi)); 22-bit coverage
__device__ __forceinline__ void split_h(float x, unsigned short& h, unsigned short& l) {
    __half hb = __float2half_rn(x);
    float r = x - __half2float(hb);
    __half lb = __float2half_rn(r);
    h = __half_as_ushort(hb);
    l = __half_as_ushort(lb);
}

// smem: per-stage A (up to 2 splits x 128 rows x 64 fp16 = 128B rows,
// XOR-swizzled) and B (up to 2 splits x 256 rows x 64 fp16).
#define A_SP        16384                 // 128 * 128B
#define B_SP        32768                 // 256 * 128B
#define STAGE_BYTES (2 * A_SP + 2 * B_SP) // 98304
#define SMEM_TOTAL  (2 * STAGE_BYTES)     // 196608
#define SWB(kbyte, r) ((kbyte) ^ (((r) & 7) << 4))

#define NPERSIST 148                      // persistent grid (1 CTA/SM)

// ---------------------------------------------------------------------------
// Split-fp16 mma.sync GEMM. Block tile 128x256, 256 threads (8 warps, 2x4,
// warp tile 64x64), K chunks of 64, 2-stage cp.async double buffer.
//   CFG 0 (proj):   single-tile per CTA. z selects q/k/v.
//                   A = fp32 input (split in staging), B = g_wh/g_wl[z],
//                   K=256, 3 MMAs/product. Epilogue: +bias -> z<2 split to
//                   g_qh/g_ql | g_kh/g_kl; z=2 transpose -> g_vth (hi only).
//   CFG 1 (scores): PERSISTENT. A=q, B=k, K=256, 3 MMAs/product, fp32->g_S.
//   CFG 2 (ctx):    PERSISTENT. A = fp16 P rows in g_S (stride 8192 ushorts),
//                   B = vt hi, K=4096, 1 MMA/product, fp32 -> out.
// Persistent CTAs stage next tile's chunk 0 during the last compute iter so
// the loads overlap the epilogue; one cold prologue per CTA, not per tile.
// Pipeline audit: in-flight cp.async groups <= 2 at all times; NC even ->
// next-tile chunk 0 lands in buffer 0 while last compute uses buffer 1;
// __syncthreads at loop top protects buffer reuse; control flow tid-uniform.
// ---------------------------------------------------------------------------
template<int CFG>
__global__ __launch_bounds__(256, 1)
void gemm_kernel(const float* __restrict__ in_q, const float* __restrict__ in_k,
                 const float* __restrict__ in_v,
                 const float* __restrict__ bq, const float* __restrict__ bk,
                 const float* __restrict__ bv, float* __restrict__ out)
{
    constexpr int K      = (CFG == 2) ? 4096 : 256;
    constexpr int NC     = K / 64;
    constexpr int NCOMBO = (CFG == 2) ? 1 : 3;
    constexpr bool A2    = (CFG != 2);           // A has lo split?
    constexpr bool B2    = (CFG != 2);           // B has lo split?
    constexpr long long LDA = (CFG == 2) ? 8192 : 256;
    constexpr long long LDB = (CFG == 2) ? 4096 : 256;

    extern __shared__ __align__(128) char sm[];
    const uint32_t smb = smem_u32(sm);
    const int tid = threadIdx.x;
    const int w = tid >> 5, lane = tid & 31;
    const int wm = w & 1, wn = w >> 1;          // 2 x 4 warp grid

    // ldmatrix per-thread constants
    const int a_r0 = wm * 64 + (lane & 7) + ((lane >> 3) & 1) * 8;   // + mt*16
    const int a_kb = (lane >> 4) * 16;
    const int b_n0 = wn * 64 + (lane & 7) + (lane >> 4) * 8;          // + g*16
    const int b_kb = ((lane >> 3) & 1) * 16;

    // generic staged-pointer loader (presplit fp16 operands, cp.async)
    auto stageg = [&](const unsigned short* a0, const unsigned short* a1,
                      const unsigned short* b0, const unsigned short* b1, int c) {
        const uint32_t sb = smb + (c & 1) * STAGE_BYTES;
        const int k0 = c * 64;
        if (CFG == 1) {
#pragma unroll
            for (int t = tid; t < 2048; t += 256) {
                int sp = t >> 10, r = (t >> 3) & 127, kc = (t & 7) * 8;
                const unsigned short* src = (sp ? a1 : a0) + (long long)r * LDA + k0 + kc;
                CP16(sb + sp * A_SP + r * 128 + SWB(kc * 2, r), src);
            }
#pragma unroll
            for (int t = tid; t < 4096; t += 256) {
                int sp = t >> 11, r = (t >> 3) & 255, kc = (t & 7) * 8;
                const unsigned short* src = (sp ? b1 : b0) + (long long)r * LDB + k0 + kc;
                CP16(sb + 2 * A_SP + sp * B_SP + r * 128 + SWB(kc * 2, r), src);
            }
        } else {   // CFG 2: single-split A (P) and B (V hi)
#pragma unroll
            for (int t = tid; t < 1024; t += 256) {
                int r = t >> 3, kc = (t & 7) * 8;
                CP16(sb + r * 128 + SWB(kc * 2, r), a0 + (long long)r * LDA + k0 + kc);
            }
#pragma unroll
            for (int t = tid; t < 2048; t += 256) {
                int r = t >> 3, kc = (t & 7) * 8;
                CP16(sb + 2 * A_SP + r * 128 + SWB(kc * 2, r),
                     b0 + (long long)r * LDB + k0 + kc);
            }
        }
        CP_COMMIT();
    };

    auto compute = [&](int buf, float (&acc)[4][8][4]) {
        const uint32_t sa = smb + buf * STAGE_BYTES;
        const uint32_t sbb = sa + 2 * A_SP;
#pragma unroll
        for (int ks = 0; ks < 4; ks++) {
            uint32_t Ahf[4][4], Alf[4][4];
#pragma unroll
            for (int mt = 0; mt < 4; mt++) {
                int row = a_r0 + mt * 16;
                uint32_t ad = sa + row * 128 + SWB(ks * 32 + a_kb, row);
                LDSM4(Ahf[mt], ad);
                if (A2) LDSM4(Alf[mt], ad + A_SP);
            }
#pragma unroll
            for (int g = 0; g < 4; g++) {
                int nrow = b_n0 + g * 16;
                uint32_t bd = sbb + nrow * 128 + SWB(ks * 32 + b_kb, nrow);
                uint32_t Bh[4], Bl[4];
                LDSM4(Bh, bd);
                if (B2) LDSM4(Bl, bd + B_SP);
#pragma unroll
                for (int combo = 0; combo < NCOMBO; combo++)
#pragma unroll
                    for (int mt = 0; mt < 4; mt++)
#pragma unroll
                        for (int sub = 0; sub < 2; sub++) {
                            int nt = g * 2 + sub;
                            const uint32_t* af = (combo == 2) ? Alf[mt] : Ahf[mt];
                            const uint32_t* bf = (combo == 1) ? (Bl + sub * 2)
                                                              : (Bh + sub * 2);
                            MMA(acc[mt][nt], af, bf);
                        }
            }
        }
    };

    if constexpr (CFG == 0) {
        // ---------------- projection: one tile per CTA ----------------
        const int m0 = blockIdx.x * 128;
        const int z = blockIdx.z;
        const float* Afp = (z == 0 ? in_q : z == 1 ? in_k : in_v)
                           + (long long)m0 * 256;
        const unsigned short* b0 = g_wh[z];
        const unsigned short* b1 = g_wl[z];

        float acc[4][8][4] = {};

        auto stage0 = [&](int c) {
            const uint32_t sb = smb + (c & 1) * STAGE_BYTES;
            char* sbp = sm + (c & 1) * STAGE_BYTES;
            const int k0 = c * 64;
#pragma unroll
            for (int t = tid; t < 2048; t += 256) {
                int r = t >> 4, kq = (t & 15) * 4;
                float4 v = *reinterpret_cast<const float4*>(Afp + r * 256 + k0 + kq);
                ushort4 hh, ll;
                split_h(v.x, hh.x, ll.x); split_h(v.y, hh.y, ll.y);
                split_h(v.z, hh.z, ll.z); split_h(v.w, hh.w, ll.w);
                int off = r * 128 + SWB(kq * 2, r);
                *reinterpret_cast<ushort4*>(sbp + off)        = hh;
                *reinterpret_cast<ushort4*>(sbp + A_SP + off) = ll;
            }
#pragma unroll
            for (int t = tid; t < 4096; t += 256) {
                int sp = t >> 11, r = (t >> 3) & 255, kc = (t & 7) * 8;
                const unsigned short* src = (sp ? b1 : b0) + (long long)r * 256 + k0 + kc;
                CP16(sb + 2 * A_SP + sp * B_SP + r * 128 + SWB(kc * 2, r), src);
            }
            CP_COMMIT();
        };

        stage0(0);
        for (int c = 0; c < 4; c++) {
            __syncthreads();
            if (c + 1 < 4) stage0(c + 1);
            if (c + 1 < 4) CP_WAIT1(); else CP_WAIT0();
            __syncthreads();
            compute(c & 1, acc);
        }
        __syncthreads();

        const float* bias = (z == 0) ? bq : (z == 1) ? bk : bv;
        if (z < 2) {
            unsigned short* DH = (z == 0) ? g_qh : g_kh;
            unsigned short* DL = (z == 0) ? g_ql : g_kl;
#pragma unroll
            for (int mt = 0; mt < 4; mt++)
#pragma unroll
                for (int nt = 0; nt < 8; nt++) {
                    int m  = m0 + wm * 64 + mt * 16 + (lane >> 2);
                    int ng = wn * 64 + nt * 8 + (lane & 3) * 2;
                    float b0f = bias[ng], b1f = bias[ng + 1];
                    float* a = acc[mt][nt];
                    ushort2 h2, l2;
                    split_h(a[0] + b0f, h2.x, l2.x); split_h(a[1] + b1f, h2.y, l2.y);
                    *reinterpret_cast<ushort2*>(&DH[(long long)m * 256 + ng]) = h2;
                    *reinterpret_cast<ushort2*>(&DL[(long long)m * 256 + ng]) = l2;
                    split_h(a[2] + b0f, h2.x, l2.x); split_h(a[3] + b1f, h2.y, l2.y);
                    *reinterpret_cast<ushort2*>(&DH[(long long)(m + 8) * 256 + ng]) = h2;
                    *reinterpret_cast<ushort2*>(&DL[(long long)(m + 8) * 256 + ng]) = l2;
                }
        } else {
            // V: transpose through smem -> g_vth (hi only) [b][d][sq]
            float* Cs = reinterpret_cast<float*>(sm);      // [128][260]
#pragma unroll
            for (int mt = 0; mt < 4; mt++)
#pragma unroll
                for (int nt = 0; nt < 8; nt++) {
                    int ml = wm * 64 + mt * 16 + (lane >> 2);
                    int nl = wn * 64 + nt * 8 + (lane & 3) * 2;
                    float b0f = bias[nl], b1f = bias[nl + 1];
                    float* a = acc[mt][nt];
                    *reinterpret_cast<float2*>(&Cs[ml * 260 + nl])
                        = make_float2(a[0] + b0f, a[1] + b1f);
                    *reinterpret_cast<float2*>(&Cs[(ml + 8) * 260 + nl])
                        = make_float2(a[2] + b0f, a[3] + b1f);
                }
            __syncthreads();
            int nl = tid;
            long long bb = m0 >> 12;
            int sq0 = m0 & 4095;
            long long obase = bb * (long long)DIM * SEQ + (long long)nl * SEQ + sq0;
#pragma unroll
            for (int j = 0; j < 32; j++) {
                int ml = j * 4;
                ushort4 hh;
                hh.x = __half_as_ushort(__float2half_rn(Cs[(ml + 0) * 260 + nl]));
                hh.y = __half_as_ushort(__float2half_rn(Cs[(ml + 1) * 260 + nl]));
                hh.z = __half_as_ushort(__float2half_rn(Cs[(ml + 2) * 260 + nl]));
                hh.w = __half_as_ushort(__float2half_rn(Cs[(ml + 3) * 260 + nl]));
                *reinterpret_cast<ushort4*>(&g_vth[obase + ml]) = hh;
            }
        }
    } else {
        // ---------------- persistent scores / ctx ----------------
        constexpr int MT = SEQ / 128;                    // 32 m-tiles
        constexpr int NT = (CFG == 1) ? (SEQ / 256) : 1; // 16 or 1 n-tiles
        constexpr int TILES = MT * NT * NBATCH;          // 4096 or 256

        auto tile_ptrs = [&](int t, const unsigned short*& a0, const unsigned short*& a1,
                             const unsigned short*& b0, const unsigned short*& b1,
                             int& m0, int& n0, int& z) {
            int bx = t % MT;
            int by = (t / MT) % NT;
            z = t / (MT * NT);
            m0 = bx * 128; n0 = by * 256;
            long long b = z;
            if (CFG == 1) {
                a0 = g_qh + (b * SEQ + m0) * 256;
                a1 = g_ql + (b * SEQ + m0) * 256;
                b0 = g_kh + (b * SEQ + n0) * 256;
                b1 = g_kl + (b * SEQ + n0) * 256;
            } else {
                a0 = reinterpret_cast<const unsigned short*>(g_S)
                     + b * SEQ * 8192 + (long long)m0 * 8192;
                a1 = a0;
                b0 = g_vth + b * (long long)DIM * SEQ;
                b1 = b0;
            }
        };

        const int t0 = (int)blockIdx.x;
        if (t0 >= TILES) return;

        {   // prologue: stage chunk 0 of the first tile
            const unsigned short *a0, *a1, *b0, *b1; int m0, n0, z;
            tile_ptrs(t0, a0, a1, b0, b1, m0, n0, z);
            stageg(a0, a1, b0, b1, 0);
        }

        for (int t = t0; t < TILES; t += gridDim.x) {
            const unsigned short *a0, *a1, *b0, *b1; int m0, n0, z;
            tile_ptrs(t, a0, a1, b0, b1, m0, n0, z);
            const int tn = t + gridDim.x;
            const bool hasnext = tn < TILES;

            float acc[4][8][4] = {};
            for (int c = 0; c < NC; c++) {
                __syncthreads();               // prior compute done before reuse
                if (c + 1 < NC) {
                    stageg(a0, a1, b0, b1, c + 1);
                } else if (hasnext) {
                    const unsigned short *na0, *na1, *nb0, *nb1; int nm, nn, nz;
                    tile_ptrs(tn, na0, na1, nb0, nb1, nm, nn, nz);
                    stageg(na0, na1, nb0, nb1, 0);   // overlaps this epilogue
                }
                if (c + 1 < NC || hasnext) CP_WAIT1(); else CP_WAIT0();
                __syncthreads();
                compute(c & 1, acc);
            }

            // epilogue (no smem use -> overlaps next tile's chunk-0 loads)
            if (CFG == 1) {
                long long base = (long long)z * SEQ * SEQ;
#pragma unroll
                for (int mt = 0; mt < 4; mt++)
#pragma unroll
                    for (int nt = 0; nt < 8; nt++) {
                        int m = m0 + wm * 64 + mt * 16 + (lane >> 2);
                        int n = n0 + wn * 64 + nt * 8 + (lane & 3) * 2;
                        float* a = acc[mt][nt];
                        *reinterpret_cast<float2*>(
                            &g_S[base + (long long)m * 4096 + n])
                            = make_float2(a[0], a[1]);
                        *reinterpret_cast<float2*>(
                            &g_S[base + (long long)(m + 8) * 4096 + n])
                            = make_float2(a[2], a[3]);
                    }
            } else {
#pragma unroll
                for (int mt = 0; mt < 4; mt++)
#pragma unroll
                    for (int nt = 0; nt < 8; nt++) {
                        int m = m0 + wm * 64 + mt * 16 + (lane >> 2);
                        int n = wn * 64 + nt * 8 + (lane & 3) * 2;
                        float* a = acc[mt][nt];
                        long long rb = ((long long)z * SEQ + m) * 256 + n;
                        *reinterpret_cast<float2*>(&out[rb])
                            = make_float2(a[0], a[1]);
                        *reinterpret_cast<float2*>(&out[rb + 2048])
                            = make_float2(a[2], a[3]);
                    }
            }
        }
    }
}

// ---------------------------------------------------------------------------
// merged weight split: Wq/Wk/Wv -> g_wh/g_wl (fp16 hi/lo)
// ---------------------------------------------------------------------------
__global__ __launch_bounds__(256) void split_w_kernel(
    const float* __restrict__ Wq, const float* __restrict__ Wk,
    const float* __restrict__ Wv)
{
    int gi = blockIdx.x * 256 + threadIdx.x;   // 0..49151 (3 * 16384 float4)
    int wsel = gi >> 14;
    int i = gi & 16383;
    const float* x = (wsel == 0) ? Wq : (wsel == 1) ? Wk : Wv;
    float4 v = reinterpret_cast<const float4*>(x)[i];
    ushort4 hh, ll;
    split_h(v.x, hh.x, ll.x);
    split_h(v.y, hh.y, ll.y);
    split_h(v.z, hh.z, ll.z);
    split_h(v.w, hh.w, ll.w);
    reinterpret_cast<ushort4*>(g_wh[wsel])[i] = hh;
    reinterpret_cast<ushort4*>(g_wl[wsel])[i] = ll;
}

// ---------------------------------------------------------------------------
// softmax over rows of 4096 in g_S, IN PLACE: fp32 row -> single fp16 P
// (first 8KB of the row). Row fully read into registers first. (85% HBM.)
// ---------------------------------------------------------------------------
__global__ __launch_bounds__(256, 1) void softmax_kernel()
{
    __shared__ float red[8];
    const int tid = threadIdx.x;
    const int w = tid >> 5, lane = tid & 31;
    float* S = g_S + (long long)blockIdx.x * 4096;

    float4 x[4];
#pragma unroll
    for (int j = 0; j < 4; j++)
        x[j] = *reinterpret_cast<const float4*>(S + (j * 256 + tid) * 4);

    float mx = -1e30f;
#pragma unroll
    for (int j = 0; j < 4; j++)
        mx = fmaxf(mx, fmaxf(fmaxf(x[j].x, x[j].y), fmaxf(x[j].z, x[j].w)));
#pragma unroll
    for (int o = 16; o; o >>= 1) mx = fmaxf(mx, __shfl_xor_sync(~0u, mx, o));
    if (lane == 0) red[w] = mx;
    __syncthreads();
    mx = red[0];
#pragma unroll
    for (int i = 1; i < 8; i++) mx = fmaxf(mx, red[i]);
    __syncthreads();

    float p[16];
    float sum = 0.f;
#pragma unroll
    for (int j = 0; j < 4; j++) {
        p[4 * j + 0] = __expf(x[j].x - mx);
        p[4 * j + 1] = __expf(x[j].y - mx);
        p[4 * j + 2] = __expf(x[j].z - mx);
        p[4 * j + 3] = __expf(x[j].w - mx);
        sum += (p[4 * j] + p[4 * j + 1]) + (p[4 * j + 2] + p[4 * j + 3]);
    }
#pragma unroll
    for (int o = 16; o; o >>= 1) sum += __shfl_xor_sync(~0u, sum, o);
    if (lane == 0) red[w] = sum;
    __syncthreads();
    sum = 0.f;
#pragma unroll
    for (int i = 0; i < 8; i++) sum += red[i];
    float inv = 1.f / sum;
    __syncthreads();   // all reads done; safe to overwrite row

    unsigned short* Ph = reinterpret_cast<unsigned short*>(S);
#pragma unroll
    for (int j = 0; j < 4; j++) {
        ushort4 hh;
        hh.x = __half_as_ushort(__float2half_rn(p[4 * j + 0] * inv));
        hh.y = __half_as_ushort(__float2half_rn(p[4 * j + 1] * inv));
        hh.z = __half_as_ushort(__float2half_rn(p[4 * j + 2] * inv));
        hh.w = __half_as_ushort(__float2half_rn(p[4 * j + 3] * inv));
        *reinterpret_cast<ushort4*>(Ph + (j * 256 + tid) * 4) = hh;
    }
}

// ---------------------------------------------------------------------------
extern "C" void kernel_launch(void* const* d_in, const int* in_sizes, int n_in,
                              void* d_out, int out_size)
{
    (void)in_sizes; (void)n_in; (void)out_size;
    const float* query  = (const float*)d_in[0];
    const float* keys   = (const float*)d_in[1];
    const float* values = (const float*)d_in[2];
    const float* Wq     = (const float*)d_in[3];
    const float* bq     = (const float*)d_in[4];
    const float* Wk     = (const float*)d_in[5];
    const float* bk     = (const float*)d_in[6];
    const float* Wv     = (const float*)d_in[7];
    const float* bv     = (const float*)d_in[8];
    float* out = (float*)d_out;

    cudaFuncSetAttribute(gemm_kernel<0>, cudaFuncAttributeMaxDynamicSharedMemorySize, SMEM_TOTAL);
    cudaFuncSetAttribute(gemm_kernel<1>, cudaFuncAttributeMaxDynamicSharedMemorySize, SMEM_TOTAL);
    cudaFuncSetAttribute(gemm_kernel<2>, cudaFuncAttributeMaxDynamicSharedMemorySize, SMEM_TOTAL);

    // 1) weight splits (one launch)
    split_w_kernel<<<192, 256>>>(Wq, Wk, Wv);

    // 2) all three projections (one launch; z selects q/k/v)
    gemm_kernel<0><<<dim3(NTOK / 128, 1, 3), 256, SMEM_TOTAL>>>(
        query, keys, values, bq, bk, bv, nullptr);

    // 3) scores, persistent (4096 tiles over 148 CTAs)
    gemm_kernel<1><<<NPERSIST, 256, SMEM_TOTAL>>>(
        nullptr, nullptr, nullptr, nullptr, nullptr, nullptr, nullptr);

    // 4) softmax, in place (fp32 row -> single fp16 P)
    softmax_kernel<<<NTOK, 256>>>();

    // 5) context, persistent (256 tiles over 148 CTAs)
    gemm_kernel<2><<<NPERSIST, 256, SMEM_TOTAL>>>(
        nullptr, nullptr, nullptr, nullptr, nullptr, nullptr, out);
}

// round 15
// speedup vs baseline: 1.5072x; 1.0695x over previous
#include <cuda_runtime.h>
#include <cuda_fp16.h>
#include <stdint.h>

#define NBATCH 8
#define SEQ    4096
#define DIM    256
#define NTOK   (NBATCH * SEQ)                 // 32768
#define PROJ_ELEMS (NTOK * DIM)               // 8388608
#define S_ELEMS ((long long)NBATCH * SEQ * SEQ)

// ---------------- scratch (static device arrays) ---------------------------
// g_P: fp16 unnormalized tile-local softmax numerators p~ = 2^(s - m_tile).
__device__ __align__(16) unsigned short g_P[S_ELEMS];                 // 268 MB
__device__ __align__(16) float          g_m[NTOK * 16];               // per (row, tile) max
__device__ __align__(16) float          g_sum[NTOK * 16];             // per (row, tile) sum
__device__ __align__(16) unsigned short g_scale[NTOK * 16];           // fp16 2^(m-M)/Z
__device__ __align__(16) unsigned short g_wh[3][DIM * DIM];
__device__ __align__(16) unsigned short g_wl[3][DIM * DIM];
__device__ __align__(16) unsigned short g_qh[PROJ_ELEMS], g_ql[PROJ_ELEMS];
__device__ __align__(16) unsigned short g_kh[PROJ_ELEMS], g_kl[PROJ_ELEMS];
__device__ __align__(16) unsigned short g_vth[PROJ_ELEMS];   // V^T hi only

// ---------------- helpers ---------------------------------------------------
__device__ __forceinline__ uint32_t smem_u32(const void* p) {
    uint32_t a;
    asm("{ .reg .u64 t; cvta.to.shared.u64 t, %1; cvt.u32.u64 %0, t; }"
        : "=r"(a) : "l"(p));
    return a;
}

#define CP16(dst, src) \
    asm volatile("cp.async.cg.shared.global [%0], [%1], 16;" \
                 :: "r"(dst), "l"(src) : "memory")
#define CP_COMMIT()  asm volatile("cp.async.commit_group;" ::: "memory")
#define CP_WAIT1()   asm volatile("cp.async.wait_group 1;" ::: "memory")
#define CP_WAIT0()   asm volatile("cp.async.wait_group 0;" ::: "memory")

#define LDSM4(r, addr) \
    asm volatile("ldmatrix.sync.aligned.m8n8.x4.shared.b16 {%0,%1,%2,%3}, [%4];" \
                 : "=r"((r)[0]), "=r"((r)[1]), "=r"((r)[2]), "=r"((r)[3]) \
                 : "r"(addr))

// fp16 MMA, fp32 accumulate
#define MMA(d, a, b) \
    asm volatile("mma.sync.aligned.m16n8k16.row.col.f32.f16.f16.f32 " \
                 "{%0,%1,%2,%3},{%4,%5,%6,%7},{%8,%9},{%0,%1,%2,%3};" \
                 : "+f"((d)[0]), "+f"((d)[1]), "+f"((d)[2]), "+f"((d)[3]) \
                 : "r"((a)[0]), "r"((a)[1]), "r"((a)[2]), "r"((a)[3]), \
                   "r"((b)[0]), "r"((b)[1]))

#define HMUL2(d, s) \
    asm("mul.rn.f16x2 %0, %0, %1;" : "+r"(d) : "r"(s))

// fp32 -> fp16 hi/lo split (hi = rn(x), lo = rn(x - hi)); 22-bit coverage
__device__ __forceinline__ void split_h(float x, unsigned short& h, unsigned short& l) {
    __half hb = __float2half_rn(x);
    float r = x - __half2float(hb);
    __half lb = __float2half_rn(r);
    h = __half_as_ushort(hb);
    l = __half_as_ushort(lb);
}

__device__ __forceinline__ unsigned short f2h(float x) {
    return __half_as_ushort(__float2half_rn(x));
}

#define A_SP        16384                 // 128 * 128B
#define B_SP        32768                 // 256 * 128B
#define STAGE_BYTES (2 * A_SP + 2 * B_SP) // 98304
#define SMEM_TOTAL  (2 * STAGE_BYTES)     // 196608
#define SWB(kbyte, r) ((kbyte) ^ (((r) & 7) << 4))

#define NPERSIST 148
#define LOG2E 1.44269504f

// ---------------------------------------------------------------------------
// Split-fp16 mma.sync GEMM. Block tile 128x256, 256 threads (8 warps, 2x4,
// warp tile 64x64), K chunks of 64, 2-stage cp.async double buffer.
//   CFG 0 (proj):   one tile per CTA. z selects q/k/v. Epilogue: +bias ->
//                   z=0: *LOG2E, split -> g_qh/g_ql (log2-domain scores);
//                   z=1: split -> g_kh/g_kl; z=2: transpose -> g_vth (hi).
//   CFG 1 (scores): PERSISTENT. s' = q'.k (log2 domain). Epilogue: per-row
//                   tile max m_t, p~ = 2^(s'-m_t) -> fp16 g_P; (m_t, sum) aux.
//                   NOTE: epilogue reuses buffer-1 smem as scratch R -> a
//                   __syncthreads is REQUIRED after the last compute before
//                   the first R write (races with other warps' LDSM reads
//                   of buffer 1 otherwise -> NaN; this was the R14 bug).
//   CFG 2 (ctx):    PERSISTENT. A = fp16 p~ (ld 4096), scaled post-LDSM by
//                   fp16 scale = 2^(m_t-M)/Z; B = vt hi; 1 MMA/product.
// ---------------------------------------------------------------------------
template<int CFG>
__global__ __launch_bounds__(256, 1)
void gemm_kernel(const float* __restrict__ in_q, const float* __restrict__ in_k,
                 const float* __restrict__ in_v,
                 const float* __restrict__ bq, const float* __restrict__ bk,
                 const float* __restrict__ bv, float* __restrict__ out)
{
    constexpr int K      = (CFG == 2) ? 4096 : 256;
    constexpr int NC     = K / 64;
    constexpr int NCOMBO = (CFG == 2) ? 1 : 3;
    constexpr bool A2    = (CFG != 2);
    constexpr bool B2    = (CFG != 2);
    constexpr long long LDA = (CFG == 2) ? 4096 : 256;
    constexpr long long LDB = (CFG == 2) ? 4096 : 256;

    extern __shared__ __align__(128) char sm[];
    const uint32_t smb = smem_u32(sm);
    const int tid = threadIdx.x;
    const int w = tid >> 5, lane = tid & 31;
    const int wm = w & 1, wn = w >> 1;          // 2 x 4 warp grid

    const int a_r0 = wm * 64 + (lane & 7) + ((lane >> 3) & 1) * 8;
    const int a_kb = (lane >> 4) * 16;
    const int b_n0 = wn * 64 + (lane & 7) + (lane >> 4) * 8;
    const int b_kb = ((lane >> 3) & 1) * 16;

    auto stageg = [&](const unsigned short* a0, const unsigned short* a1,
                      const unsigned short* b0, const unsigned short* b1, int c) {
        const uint32_t sb = smb + (c & 1) * STAGE_BYTES;
        const int k0 = c * 64;
        if (CFG == 1) {
#pragma unroll
            for (int t = tid; t < 2048; t += 256) {
                int sp = t >> 10, r = (t >> 3) & 127, kc = (t & 7) * 8;
                const unsigned short* src = (sp ? a1 : a0) + (long long)r * LDA + k0 + kc;
                CP16(sb + sp * A_SP + r * 128 + SWB(kc * 2, r), src);
            }
#pragma unroll
            for (int t = tid; t < 4096; t += 256) {
                int sp = t >> 11, r = (t >> 3) & 255, kc = (t & 7) * 8;
                const unsigned short* src = (sp ? b1 : b0) + (long long)r * LDB + k0 + kc;
                CP16(sb + 2 * A_SP + sp * B_SP + r * 128 + SWB(kc * 2, r), src);
            }
        } else {   // CFG 2: single-split A (p~) and B (V hi)
#pragma unroll
            for (int t = tid; t < 1024; t += 256) {
                int r = t >> 3, kc = (t & 7) * 8;
                CP16(sb + r * 128 + SWB(kc * 2, r), a0 + (long long)r * LDA + k0 + kc);
            }
#pragma unroll
            for (int t = tid; t < 2048; t += 256) {
                int r = t >> 3, kc = (t & 7) * 8;
                CP16(sb + 2 * A_SP + r * 128 + SWB(kc * 2, r),
                     b0 + (long long)r * LDB + k0 + kc);
            }
        }
        CP_COMMIT();
    };

    auto compute = [&](int buf, float (&acc)[4][8][4], const uint32_t (*s2)[2]) {
        const uint32_t sa = smb + buf * STAGE_BYTES;
        const uint32_t sbb = sa + 2 * A_SP;
#pragma unroll
        for (int ks = 0; ks < 4; ks++) {
            uint32_t Ahf[4][4], Alf[4][4];
#pragma unroll
            for (int mt = 0; mt < 4; mt++) {
                int row = a_r0 + mt * 16;
                uint32_t ad = sa + row * 128 + SWB(ks * 32 + a_kb, row);
                LDSM4(Ahf[mt], ad);
                if (CFG == 2) {
                    // regs 0,2 = row g; regs 1,3 = row g+8
                    HMUL2(Ahf[mt][0], s2[mt][0]);
                    HMUL2(Ahf[mt][2], s2[mt][0]);
                    HMUL2(Ahf[mt][1], s2[mt][1]);
                    HMUL2(Ahf[mt][3], s2[mt][1]);
                }
                if (A2) LDSM4(Alf[mt], ad + A_SP);
            }
#pragma unroll
            for (int g = 0; g < 4; g++) {
                int nrow = b_n0 + g * 16;
                uint32_t bd = sbb + nrow * 128 + SWB(ks * 32 + b_kb, nrow);
                uint32_t Bh[4], Bl[4];
                LDSM4(Bh, bd);
                if (B2) LDSM4(Bl, bd + B_SP);
#pragma unroll
                for (int combo = 0; combo < NCOMBO; combo++)
#pragma unroll
                    for (int mt = 0; mt < 4; mt++)
#pragma unroll
                        for (int sub = 0; sub < 2; sub++) {
                            int nt = g * 2 + sub;
                            const uint32_t* af = (combo == 2) ? Alf[mt] : Ahf[mt];
                            const uint32_t* bf = (combo == 1) ? (Bl + sub * 2)
                                                              : (Bh + sub * 2);
                            MMA(acc[mt][nt], af, bf);
                        }
            }
        }
    };

    if constexpr (CFG == 0) {
        // ---------------- projection: one tile per CTA ----------------
        const int m0 = blockIdx.x * 128;
        const int z = blockIdx.z;
        const float* Afp = (z == 0 ? in_q : z == 1 ? in_k : in_v)
                           + (long long)m0 * 256;
        const unsigned short* b0 = g_wh[z];
        const unsigned short* b1 = g_wl[z];

        float acc[4][8][4] = {};

        auto stage0 = [&](int c) {
            const uint32_t sb = smb + (c & 1) * STAGE_BYTES;
            char* sbp = sm + (c & 1) * STAGE_BYTES;
            const int k0 = c * 64;
#pragma unroll
            for (int t = tid; t < 2048; t += 256) {
                int r = t >> 4, kq = (t & 15) * 4;
                float4 v = *reinterpret_cast<const float4*>(Afp + r * 256 + k0 + kq);
                ushort4 hh, ll;
                split_h(v.x, hh.x, ll.x); split_h(v.y, hh.y, ll.y);
                split_h(v.z, hh.z, ll.z); split_h(v.w, hh.w, ll.w);
                int off = r * 128 + SWB(kq * 2, r);
                *reinterpret_cast<ushort4*>(sbp + off)        = hh;
                *reinterpret_cast<ushort4*>(sbp + A_SP + off) = ll;
            }
#pragma unroll
            for (int t = tid; t < 4096; t += 256) {
                int sp = t >> 11, r = (t >> 3) & 255, kc = (t & 7) * 8;
                const unsigned short* src = (sp ? b1 : b0) + (long long)r * 256 + k0 + kc;
                CP16(sb + 2 * A_SP + sp * B_SP + r * 128 + SWB(kc * 2, r), src);
            }
            CP_COMMIT();
        };

        stage0(0);
        for (int c = 0; c < 4; c++) {
            __syncthreads();
            if (c + 1 < 4) stage0(c + 1);
            if (c + 1 < 4) CP_WAIT1(); else CP_WAIT0();
            __syncthreads();
            compute(c & 1, acc, nullptr);
        }
        __syncthreads();

        const float* bias = (z == 0) ? bq : (z == 1) ? bk : bv;
        if (z < 2) {
            unsigned short* DH = (z == 0) ? g_qh : g_kh;
            unsigned short* DL = (z == 0) ? g_ql : g_kl;
            const float qsc = (z == 0) ? LOG2E : 1.0f;   // q in log2 domain
#pragma unroll
            for (int mt = 0; mt < 4; mt++)
#pragma unroll
                for (int nt = 0; nt < 8; nt++) {
                    int m  = m0 + wm * 64 + mt * 16 + (lane >> 2);
                    int ng = wn * 64 + nt * 8 + (lane & 3) * 2;
                    float b0f = bias[ng], b1f = bias[ng + 1];
                    float* a = acc[mt][nt];
                    ushort2 h2, l2;
                    split_h((a[0] + b0f) * qsc, h2.x, l2.x);
                    split_h((a[1] + b1f) * qsc, h2.y, l2.y);
                    *reinterpret_cast<ushort2*>(&DH[(long long)m * 256 + ng]) = h2;
                    *reinterpret_cast<ushort2*>(&DL[(long long)m * 256 + ng]) = l2;
                    split_h((a[2] + b0f) * qsc, h2.x, l2.x);
                    split_h((a[3] + b1f) * qsc, h2.y, l2.y);
                    *reinterpret_cast<ushort2*>(&DH[(long long)(m + 8) * 256 + ng]) = h2;
                    *reinterpret_cast<ushort2*>(&DL[(long long)(m + 8) * 256 + ng]) = l2;
                }
        } else {
            float* Cs = reinterpret_cast<float*>(sm);      // [128][260]
#pragma unroll
            for (int mt = 0; mt < 4; mt++)
#pragma unroll
                for (int nt = 0; nt < 8; nt++) {
                    int ml = wm * 64 + mt * 16 + (lane >> 2);
                    int nl = wn * 64 + nt * 8 + (lane & 3) * 2;
                    float b0f = bias[nl], b1f = bias[nl + 1];
                    float* a = acc[mt][nt];
                    *reinterpret_cast<float2*>(&Cs[ml * 260 + nl])
                        = make_float2(a[0] + b0f, a[1] + b1f);
                    *reinterpret_cast<float2*>(&Cs[(ml + 8) * 260 + nl])
                        = make_float2(a[2] + b0f, a[3] + b1f);
                }
            __syncthreads();
            int nl = tid;
            long long bb = m0 >> 12;
            int sq0 = m0 & 4095;
            long long obase = bb * (long long)DIM * SEQ + (long long)nl * SEQ + sq0;
#pragma unroll
            for (int j = 0; j < 32; j++) {
                int ml = j * 4;
                ushort4 hh;
                hh.x = f2h(Cs[(ml + 0) * 260 + nl]);
                hh.y = f2h(Cs[(ml + 1) * 260 + nl]);
                hh.z = f2h(Cs[(ml + 2) * 260 + nl]);
                hh.w = f2h(Cs[(ml + 3) * 260 + nl]);
                *reinterpret_cast<ushort4*>(&g_vth[obase + ml]) = hh;
            }
        }
    } else {
        // ---------------- persistent scores / ctx ----------------
        constexpr int MT = SEQ / 128;
        constexpr int NT = (CFG == 1) ? (SEQ / 256) : 1;
        constexpr int TILES = MT * NT * NBATCH;

        auto tile_ptrs = [&](int t, const unsigned short*& a0, const unsigned short*& a1,
                             const unsigned short*& b0, const unsigned short*& b1,
                             int& m0, int& n0, int& z) {
            int bx = t % MT;
            int by = (t / MT) % NT;
            z = t / (MT * NT);
            m0 = bx * 128; n0 = by * 256;
            long long b = z;
            if (CFG == 1) {
                a0 = g_qh + (b * SEQ + m0) * 256;
                a1 = g_ql + (b * SEQ + m0) * 256;
                b0 = g_kh + (b * SEQ + n0) * 256;
                b1 = g_kl + (b * SEQ + n0) * 256;
            } else {
                a0 = g_P + (b * SEQ + m0) * 4096;
                a1 = a0;
                b0 = g_vth + b * (long long)DIM * SEQ;
                b1 = b0;
            }
        };

        auto load_scales = [&](int z, int m0, int ti, uint32_t (&s2)[4][2]) {
#pragma unroll
            for (int mt = 0; mt < 4; mt++)
#pragma unroll
                for (int h = 0; h < 2; h++) {
                    int rg = m0 + wm * 64 + mt * 16 + (lane >> 2) + h * 8;
                    unsigned short sv =
                        g_scale[((long long)z * SEQ + rg) * 16 + ti];
                    s2[mt][h] = (uint32_t)sv * 0x10001u;
                }
        };

        const int t0 = (int)blockIdx.x;
        if (t0 >= TILES) return;

        {
            const unsigned short *a0, *a1, *b0, *b1; int m0, n0, z;
            tile_ptrs(t0, a0, a1, b0, b1, m0, n0, z);
            stageg(a0, a1, b0, b1, 0);
        }

        for (int t = t0; t < TILES; t += gridDim.x) {
            const unsigned short *a0, *a1, *b0, *b1; int m0, n0, z;
            tile_ptrs(t, a0, a1, b0, b1, m0, n0, z);
            const int tn = t + gridDim.x;
            const bool hasnext = tn < TILES;

            uint32_t s2c[4][2], s2n[4][2];
            if (CFG == 2) {                 // prefetch scale groups 0, 1
                load_scales(z, m0, 0, s2c);
                load_scales(z, m0, 1, s2n);
            }

            float acc[4][8][4] = {};
            for (int c = 0; c < NC; c++) {
                __syncthreads();
                if (CFG == 2 && (c & 3) == 0 && c > 0) {
#pragma unroll
                    for (int mt = 0; mt < 4; mt++) {
                        s2c[mt][0] = s2n[mt][0]; s2c[mt][1] = s2n[mt][1];
                    }
                    if ((c >> 2) + 1 < 16) load_scales(z, m0, (c >> 2) + 1, s2n);
                }
                if (c + 1 < NC) {
                    stageg(a0, a1, b0, b1, c + 1);
                } else if (hasnext) {
                    const unsigned short *na0, *na1, *nb0, *nb1; int nm, nn, nz;
                    tile_ptrs(tn, na0, na1, nb0, nb1, nm, nn, nz);
                    stageg(na0, na1, nb0, nb1, 0);
                }
                if (c + 1 < NC || hasnext) CP_WAIT1(); else CP_WAIT0();
                __syncthreads();
                compute(c & 1, acc, s2c);
            }

            if (CFG == 1) {
                // ---- fused softmax phase 1 epilogue ----
                float mx[4][2];
#pragma unroll
                for (int mt = 0; mt < 4; mt++) {
                    float lo = -1e30f, hi = -1e30f;
#pragma unroll
                    for (int nt = 0; nt < 8; nt++) {
                        float* a = acc[mt][nt];
                        lo = fmaxf(lo, fmaxf(a[0], a[1]));
                        hi = fmaxf(hi, fmaxf(a[2], a[3]));
                    }
                    mx[mt][0] = lo; mx[mt][1] = hi;
                }
#pragma unroll
                for (int off = 1; off < 4; off <<= 1)
#pragma unroll
                    for (int mt = 0; mt < 4; mt++) {
                        mx[mt][0] = fmaxf(mx[mt][0], __shfl_xor_sync(~0u, mx[mt][0], off));
                        mx[mt][1] = fmaxf(mx[mt][1], __shfl_xor_sync(~0u, mx[mt][1], off));
                    }
                // R14 BUG FIX: all warps must finish LDSM reads of buffer 1
                // before it is reused as reduction scratch R.
                __syncthreads();
                float* R = reinterpret_cast<float*>(sm + STAGE_BYTES); // buf1 scratch
                const int g = lane >> 2;
                if ((lane & 3) == 0) {
#pragma unroll
                    for (int mt = 0; mt < 4; mt++) {
                        R[(wm * 64 + mt * 16 + g) * 4 + wn]     = mx[mt][0];
                        R[(wm * 64 + mt * 16 + g + 8) * 4 + wn] = mx[mt][1];
                    }
                }
                __syncthreads();
                float rm[4][2], sum[4][2];
#pragma unroll
                for (int mt = 0; mt < 4; mt++)
#pragma unroll
                    for (int h = 0; h < 2; h++) {
                        int r = wm * 64 + mt * 16 + g + h * 8;
                        float4 v = *reinterpret_cast<float4*>(&R[r * 4]);
                        rm[mt][h] = fmaxf(fmaxf(v.x, v.y), fmaxf(v.z, v.w));
                        sum[mt][h] = 0.f;
                    }
                unsigned short* Pb = g_P + ((long long)z * SEQ + m0) * 4096 + n0;
#pragma unroll
                for (int mt = 0; mt < 4; mt++)
#pragma unroll
                    for (int nt = 0; nt < 8; nt++) {
                        float* a = acc[mt][nt];
                        int rl = wm * 64 + mt * 16 + g;
                        int cl = wn * 64 + nt * 8 + (lane & 3) * 2;
                        float p0 = exp2f(a[0] - rm[mt][0]);
                        float p1 = exp2f(a[1] - rm[mt][0]);
                        float p2 = exp2f(a[2] - rm[mt][1]);
                        float p3 = exp2f(a[3] - rm[mt][1]);
                        sum[mt][0] += p0 + p1;
                        sum[mt][1] += p2 + p3;
                        ushort2 w0; w0.x = f2h(p0); w0.y = f2h(p1);
                        ushort2 w1; w1.x = f2h(p2); w1.y = f2h(p3);
                        *reinterpret_cast<ushort2*>(&Pb[(long long)rl * 4096 + cl]) = w0;
                        *reinterpret_cast<ushort2*>(&Pb[(long long)(rl + 8) * 4096 + cl]) = w1;
                    }
#pragma unroll
                for (int off = 1; off < 4; off <<= 1)
#pragma unroll
                    for (int mt = 0; mt < 4; mt++) {
                        sum[mt][0] += __shfl_xor_sync(~0u, sum[mt][0], off);
                        sum[mt][1] += __shfl_xor_sync(~0u, sum[mt][1], off);
                    }
                __syncthreads();   // all rm reads of R done
                if ((lane & 3) == 0) {
#pragma unroll
                    for (int mt = 0; mt < 4; mt++) {
                        R[(wm * 64 + mt * 16 + g) * 4 + wn]     = sum[mt][0];
                        R[(wm * 64 + mt * 16 + g + 8) * 4 + wn] = sum[mt][1];
                    }
                }
                __syncthreads();
                if (wn == 0 && (lane & 3) == 0) {
                    const int ti = n0 >> 8;
#pragma unroll
                    for (int mt = 0; mt < 4; mt++)
#pragma unroll
                        for (int h = 0; h < 2; h++) {
                            int r = wm * 64 + mt * 16 + g + h * 8;
                            float4 v = *reinterpret_cast<float4*>(&R[r * 4]);
                            float Z = (v.x + v.y) + (v.z + v.w);
                            long long idx = ((long long)z * SEQ + m0 + r) * 16 + ti;
                            g_m[idx] = rm[mt][h];
                            g_sum[idx] = Z;
                        }
                }
            } else {
#pragma unroll
                for (int mt = 0; mt < 4; mt++)
#pragma unroll
                    for (int nt = 0; nt < 8; nt++) {
                        int m = m0 + wm * 64 + mt * 16 + (lane >> 2);
                        int n = wn * 64 + nt * 8 + (lane & 3) * 2;
                        float* a = acc[mt][nt];
                        long long rb = ((long long)z * SEQ + m) * 256 + n;
                        *reinterpret_cast<float2*>(&out[rb])
                            = make_float2(a[0], a[1]);
                        *reinterpret_cast<float2*>(&out[rb + 2048])
                            = make_float2(a[2], a[3]);
                    }
            }
        }
    }
}

// ---------------------------------------------------------------------------
// merged weight split: Wq/Wk/Wv -> g_wh/g_wl (fp16 hi/lo)
// ---------------------------------------------------------------------------
__global__ __launch_bounds__(256) void split_w_kernel(
    const float* __restrict__ Wq, const float* __restrict__ Wk,
    const float* __restrict__ Wv)
{
    int gi = blockIdx.x * 256 + threadIdx.x;
    int wsel = gi >> 14;
    int i = gi & 16383;
    const float* x = (wsel == 0) ? Wq : (wsel == 1) ? Wk : Wv;
    float4 v = reinterpret_cast<const float4*>(x)[i];
    ushort4 hh, ll;
    split_h(v.x, hh.x, ll.x);
    split_h(v.y, hh.y, ll.y);
    split_h(v.z, hh.z, ll.z);
    split_h(v.w, hh.w, ll.w);
    reinterpret_cast<ushort4*>(g_wh[wsel])[i] = hh;
    reinterpret_cast<ushort4*>(g_wl[wsel])[i] = ll;
}

// ---------------------------------------------------------------------------
// per-row reduce: global max M, Z; scale_t = 2^(m_t - M) / Z as fp16.
// ---------------------------------------------------------------------------
__global__ __launch_bounds__(256) void reduce_kernel()
{
    int row = blockIdx.x * 256 + threadIdx.x;   // 0..NTOK-1
    long long base = (long long)row * 16;
    float m[16], s[16];
#pragma unroll
    for (int i = 0; i < 16; i++) { m[i] = g_m[base + i]; s[i] = g_sum[base + i]; }
    float M = m[0];
#pragma unroll
    for (int i = 1; i < 16; i++) M = fmaxf(M, m[i]);
    float Z = 0.f;
#pragma unroll
    for (int i = 0; i < 16; i++) { m[i] = exp2f(m[i] - M); Z += s[i] * m[i]; }
    float inv = 1.f / Z;
#pragma unroll
    for (int i = 0; i < 16; i++)
        g_scale[base + i] = f2h(m[i] * inv);
}

// ---------------------------------------------------------------------------
extern "C" void kernel_launch(void* const* d_in, const int* in_sizes, int n_in,
                              void* d_out, int out_size)
{
    (void)in_sizes; (void)n_in; (void)out_size;
    const float* query  = (const float*)d_in[0];
    const float* keys   = (const float*)d_in[1];
    const float* values = (const float*)d_in[2];
    const float* Wq     = (const float*)d_in[3];
    const float* bq     = (const float*)d_in[4];
    const float* Wk     = (const float*)d_in[5];
    const float* bk     = (const float*)d_in[6];
    const float* Wv     = (const float*)d_in[7];
    const float* bv     = (const float*)d_in[8];
    float* out = (float*)d_out;

    cudaFuncSetAttribute(gemm_kernel<0>, cudaFuncAttributeMaxDynamicSharedMemorySize, SMEM_TOTAL);
    cudaFuncSetAttribute(gemm_kernel<1>, cudaFuncAttributeMaxDynamicSharedMemorySize, SMEM_TOTAL);
    cudaFuncSetAttribute(gemm_kernel<2>, cudaFuncAttributeMaxDynamicSharedMemorySize, SMEM_TOTAL);

    // 1) weight splits
    split_w_kernel<<<192, 256>>>(Wq, Wk, Wv);

    // 2) projections (q scaled by log2e)
    gemm_kernel<0><<<dim3(NTOK / 128, 1, 3), 256, SMEM_TOTAL>>>(
        query, keys, values, bq, bk, bv, nullptr);

    // 3) scores + fused tile-softmax, persistent
    gemm_kernel<1><<<NPERSIST, 256, SMEM_TOTAL>>>(
        nullptr, nullptr, nullptr, nullptr, nullptr, nullptr, nullptr);

    // 4) per-row scale reduce (tiny)
    reduce_kernel<<<NTOK / 256, 256>>>();

    // 5) context with fragment scaling, persistent
    gemm_kernel<2><<<NPERSIST, 256, SMEM_TOTAL>>>(
        nullptr, nullptr, nullptr, nullptr, nullptr, nullptr, out);
}